// round 13
// baseline (speedup 1.0000x reference)
#include <cuda_runtime.h>
#include <math.h>
#include <stdint.h>

#define NIMG   2
#define TCAND  4768
#define NWORDS 149
#define STOT   261888
#define SCALE_CLAMP 4.135166556742356f
#define MASKW  (NIMG * TCAND * NWORDS)   // 1420864 words

// ------------------ static device scratch ------------------
__device__ float    g_scores[NIMG * STOT];
__device__ float4   g_boxes [NIMG * STOT];
__device__ unsigned g_hist[10 * 256];
__device__ unsigned g_prefix[10];
__device__ unsigned g_krem[10];
__device__ unsigned g_kth[10];
__device__ unsigned g_needed[10];
__device__ unsigned g_lcnt[10];
__device__ int      g_llist[10 * 1000];
__device__ float    g_cand_s[NIMG * TCAND];
__device__ float4   g_cand_b[NIMG * TCAND];
__device__ float    g_sorted_s[NIMG * TCAND];
__device__ float4   g_sorted_b[NIMG * TCAND];
__device__ float4   g_sorted_ob[NIMG * TCAND];
__device__ unsigned g_validw[NIMG * NWORDS];
__device__ unsigned g_mask[MASKW];

// ------------------ level tables ------------------
__constant__ int   c_H[5]      = {256, 128, 64, 32, 16};
__constant__ int   c_HW[5]     = {65536, 16384, 4096, 1024, 256};
__constant__ float c_stride[5] = {4.f, 8.f, 16.f, 32.f, 64.f};
__constant__ int   c_soff[5]   = {0, 196608, 245760, 258048, 261120};
__constant__ int   c_L[5]      = {196608, 49152, 12288, 3072, 768};
__constant__ int   c_k[5]      = {1000, 1000, 1000, 1000, 768};

struct Feats { const float* p[5]; };
struct AnchorP { double cw[15]; double ch[15]; };

// ------------------ helpers ------------------
__device__ __forceinline__ unsigned f2key(float f) {
    unsigned u = __float_as_uint(f);
    return (u & 0x80000000u) ? ~u : (u | 0x80000000u);
}
__device__ __forceinline__ float clip1024(float v) { return fminf(fmaxf(v, 0.f), 1024.f); }
__device__ __forceinline__ void ffma2(unsigned long long& d, unsigned long long a, unsigned long long b) {
    asm("fma.rn.f32x2 %0, %1, %2, %0;" : "+l"(d) : "l"(a), "l"(b));
}
__device__ __forceinline__ unsigned long long dup2(float x) {
    unsigned long long r;
    asm("mov.b64 %0, {%1, %1};" : "=l"(r) : "f"(x));
    return r;
}
__device__ __forceinline__ float2 unpack2(unsigned long long v) {
    float2 r;
    asm("mov.b64 {%0, %1}, %2;" : "=f"(r.x), "=f"(r.y) : "l"(v));
    return r;
}

// smem layout (floats):
// As [2][16][256] @ 0       (8192)   (reused as Tacc [64][16] in head phase)
// Bs [2][16][64]  @ 8192    (2048)
// T  [256][67]    @ 10240   (17152)
// sw [15][256]    @ 27392   (3840)   total 31232 floats = 124928 B
#define SM_BS 8192
#define SM_T  10240
#define SM_SW 27392
#define TSTRIDE 67
#define CONV_SMEM_B (31232 * 4)

// ------------------ fused FFMA2 conv3x3 + head, 256co x 64px tiles ------------------
// grid: x = 1364 tiles (1024,256,64,16,4), y = img. 256 threads.
__global__ __launch_bounds__(256, 1) void conv_head_all(
    Feats feats, const float* __restrict__ wgt, const float* __restrict__ bias,
    const float* __restrict__ w_obj, const float* __restrict__ b_obj,
    const float* __restrict__ w_delta, const float* __restrict__ b_delta,
    AnchorP ap)
{
    extern __shared__ __align__(16) float sm[];
    float* As = sm;
    float* Bs = sm + SM_BS;
    float* T  = sm + SM_T;
    float* sw = sm + SM_SW;

    const int tid = threadIdx.x;
    const int tx = tid & 15, ty = tid >> 4;

    for (int i = tid; i < 15 * 256; i += 256) {
        int row = i >> 8, c = i & 255;
        sw[i] = (row < 3) ? w_obj[row * 256 + c] : w_delta[(row - 3) * 256 + c];
    }

    int bx = blockIdx.x;
    int lvl, pt;
    if      (bx < 1024) { lvl = 0; pt = bx; }
    else if (bx < 1280) { lvl = 1; pt = bx - 1024; }
    else if (bx < 1344) { lvl = 2; pt = bx - 1280; }
    else if (bx < 1360) { lvl = 3; pt = bx - 1344; }
    else                { lvl = 4; pt = bx - 1360; }
    const int W  = c_H[lvl];
    const int HW = c_HW[lvl];
    const int n  = blockIdx.y;
    const int p0 = pt * 64;
    const float* inN = feats.p[lvl] + (size_t)n * 256 * HW;

    unsigned long long acc2[8][4];
#pragma unroll
    for (int i = 0; i < 8; i++)
#pragma unroll
        for (int j = 0; j < 4; j++) acc2[i][j] = 0ULL;

    // producers: A: co=tid, 16 k/chunk. B: px=tid&63, kq=tid>>6 -> 4 k/chunk.
    const int bpx = tid & 63;
    const int bkq = (tid >> 6) * 4;
    const float* wrow = wgt + (size_t)tid * 2304;
    const int p   = p0 + bpx;
    const int y0p = p / W;
    const int x0p = p - y0p * W;

    float4 avq[4];
    float  bv[4];

#pragma unroll
    for (int r = 0; r < 4; r++)
        avq[r] = *reinterpret_cast<const float4*>(wrow + r * 4);
#pragma unroll
    for (int q = 0; q < 4; q++) {
        int k  = bkq + q;
        int ci = k / 9;
        int rr = k - ci * 9;
        int ky = rr / 3;
        int kx = rr - ky * 3;
        int yy = y0p + ky - 1;
        int xx = x0p + kx - 1;
        float v = 0.f;
        if ((unsigned)yy < (unsigned)W && (unsigned)xx < (unsigned)W)
            v = inN[(size_t)ci * HW + yy * W + xx];
        bv[q] = v;
    }
    {
#pragma unroll
        for (int r = 0; r < 4; r++) {
            float wv[4] = {avq[r].x, avq[r].y, avq[r].z, avq[r].w};
#pragma unroll
            for (int q = 0; q < 4; q++) As[(r * 4 + q) * 256 + tid] = wv[q];
        }
#pragma unroll
        for (int q = 0; q < 4; q++) Bs[(bkq + q) * 64 + bpx] = bv[q];
    }
    __syncthreads();

    for (int c0 = 0; c0 < 144; c0++) {
        const int s = c0 & 1;
        const bool more = (c0 + 1) < 144;
        if (more) {
            const float* w2 = wrow + (c0 + 1) * 16;
#pragma unroll
            for (int r = 0; r < 4; r++)
                avq[r] = *reinterpret_cast<const float4*>(w2 + r * 4);
#pragma unroll
            for (int q = 0; q < 4; q++) {
                int k  = (c0 + 1) * 16 + bkq + q;
                int ci = k / 9;
                int rr = k - ci * 9;
                int ky = rr / 3;
                int kx = rr - ky * 3;
                int yy = y0p + ky - 1;
                int xx = x0p + kx - 1;
                float v = 0.f;
                if ((unsigned)yy < (unsigned)W && (unsigned)xx < (unsigned)W)
                    v = inN[(size_t)ci * HW + yy * W + xx];
                bv[q] = v;
            }
        }
        const float* Ab = As + s * 16 * 256;
        const float* Bb = Bs + s * 16 * 64;
#pragma unroll
        for (int kk = 0; kk < 16; kk++) {
            unsigned long long a2[8];
#pragma unroll
            for (int q = 0; q < 4; q++) {
                ulonglong2 tt = *reinterpret_cast<const ulonglong2*>(&Ab[kk * 256 + ty * 16 + q * 4]);
                a2[2 * q] = tt.x; a2[2 * q + 1] = tt.y;
            }
            float4 bq = *reinterpret_cast<const float4*>(&Bb[kk * 64 + tx * 4]);
            unsigned long long b2[4];
            b2[0] = dup2(bq.x); b2[1] = dup2(bq.y);
            b2[2] = dup2(bq.z); b2[3] = dup2(bq.w);
#pragma unroll
            for (int i = 0; i < 8; i++)
#pragma unroll
                for (int j = 0; j < 4; j++)
                    ffma2(acc2[i][j], a2[i], b2[j]);
        }
        if (more) {
            float* Ad = As + (s ^ 1) * 16 * 256;
            float* Bd = Bs + (s ^ 1) * 16 * 64;
#pragma unroll
            for (int r = 0; r < 4; r++) {
                float wv[4] = {avq[r].x, avq[r].y, avq[r].z, avq[r].w};
#pragma unroll
                for (int q = 0; q < 4; q++) Ad[(r * 4 + q) * 256 + tid] = wv[q];
            }
#pragma unroll
            for (int q = 0; q < 4; q++) Bd[(bkq + q) * 64 + bpx] = bv[q];
        }
        __syncthreads();
    }

    // ---- epilogue: bias + relu -> T[co][px] (stride 67) ----
#pragma unroll
    for (int i = 0; i < 8; i++) {
        int co = ty * 16 + 2 * i;
        float bb0 = bias[co], bb1 = bias[co + 1];
        float* t0 = T + (size_t)co * TSTRIDE;
        float* t1 = t0 + TSTRIDE;
#pragma unroll
        for (int j = 0; j < 4; j++) {
            float2 v = unpack2(acc2[i][j]);
            int px = tx * 4 + j;
            t0[px] = fmaxf(v.x + bb0, 0.f);
            t1[px] = fmaxf(v.y + bb1, 0.f);
        }
    }
    __syncthreads();

    // ---- head: 4 threads/px over disjoint row groups; exact fmaf chain per (px,row) ----
    float* Tacc = As;   // [64][16], As free now
    {
        const int px = tid >> 2;
        const int rg = (tid & 3) * 4;
        float acc[4] = {0.f, 0.f, 0.f, 0.f};
        for (int c = 0; c < 256; c++) {
            float v = T[(size_t)c * TSTRIDE + px];
#pragma unroll
            for (int rr = 0; rr < 4; rr++) {
                int row = rg + rr;
                if (row < 15) acc[rr] = fmaf(v, sw[row * 256 + c], acc[rr]);
            }
        }
#pragma unroll
        for (int rr = 0; rr < 4; rr++) {
            int row = rg + rr;
            if (row < 15) Tacc[px * 16 + row] = acc[rr];
        }
    }
    __syncthreads();

    if (tid < 64) {
        const int px = tid;
        const int pg = p0 + px;
        float acc[15];
#pragma unroll
        for (int i = 0; i < 15; i++) acc[i] = Tacc[px * 16 + i];
        const float stride = c_stride[lvl];
        float gx = (float)(pg % W) * stride;
        float gy = (float)(pg / W) * stride;
#pragma unroll
        for (int a = 0; a < 3; a++) {
            float s  = acc[a] + b_obj[a];
            float dx = acc[3 + a * 4 + 0] + b_delta[a * 4 + 0];
            float dy = acc[3 + a * 4 + 1] + b_delta[a * 4 + 1];
            float dw = fminf(acc[3 + a * 4 + 2] + b_delta[a * 4 + 2], SCALE_CLAMP);
            float dh = fminf(acc[3 + a * 4 + 3] + b_delta[a * 4 + 3], SCALE_CLAMP);
            double CW = ap.cw[lvl * 3 + a], CH = ap.ch[lvl * 3 + a];
            float x0 = (float)((double)gx + CW);
            float x1 = (float)((double)gx - CW);
            float y0 = (float)((double)gy + CH);
            float y1 = (float)((double)gy - CH);
            float aw = x1 - x0, ah = y1 - y0;
            float acx = x0 + 0.5f * aw, acy = y0 + 0.5f * ah;
            float pcx = dx * aw + acx;
            float pcy = dy * ah + acy;
            float pw = expf(dw) * aw;
            float ph = expf(dh) * ah;
            float4 bx4;
            bx4.x = clip1024(pcx - 0.5f * pw);
            bx4.y = clip1024(pcy - 0.5f * ph);
            bx4.z = clip1024(pcx + 0.5f * pw);
            bx4.w = clip1024(pcy + 0.5f * ph);
            int idx = n * STOT + c_soff[lvl] + pg * 3 + a;
            g_scores[idx] = s;
            g_boxes[idx]  = bx4;
        }
    }
}

// ------------------ mask clear (replay determinism) ------------------
__global__ void clear_mask() {
    size_t i = (size_t)blockIdx.x * 1024 + threadIdx.x;
    if (i * 4 + 3 < MASKW)
        *reinterpret_cast<uint4*>(g_mask + i * 4) = make_uint4(0, 0, 0, 0);
    else
        for (size_t w = i * 4; w < MASKW; w++) g_mask[w] = 0;
}

// ------------------ level-parallel radix-select ------------------
__global__ void init_select() {
    int s = blockIdx.x;
    if (threadIdx.x == 0) { g_prefix[s] = 0; g_krem[s] = (unsigned)c_k[s >> 1]; g_lcnt[s] = 0; }
    g_hist[s * 256 + threadIdx.x] = 0;
}

__global__ void hist_kernel(int round) {
    __shared__ unsigned sh[256];
    int n = blockIdx.y, lvl = blockIdx.z;
    int s = lvl * 2 + n;
    sh[threadIdx.x] = 0;
    __syncthreads();
    unsigned pfx = g_prefix[s];
    int shift = 24 - 8 * round;
    unsigned maskhi = (round == 0) ? 0u : (0xFFFFFFFFu << (shift + 8));
    int L = c_L[lvl];
    const float* sc = g_scores + n * STOT + c_soff[lvl];
    for (int i = blockIdx.x * blockDim.x + threadIdx.x; i < L; i += gridDim.x * blockDim.x) {
        unsigned key = f2key(sc[i]);
        if (((key ^ pfx) & maskhi) == 0)
            atomicAdd(&sh[(key >> shift) & 255], 1u);
    }
    __syncthreads();
    if (sh[threadIdx.x]) atomicAdd(&g_hist[s * 256 + threadIdx.x], sh[threadIdx.x]);
}

__global__ void pick_kernel(int round) {
    int s = blockIdx.x;
    __shared__ unsigned h[256];
    h[threadIdx.x] = g_hist[s * 256 + threadIdx.x];
    __syncthreads();
    g_hist[s * 256 + threadIdx.x] = 0;
    if (threadIdx.x == 0) {
        int shift = 24 - 8 * round;
        unsigned kr = g_krem[s];
        unsigned cum = 0;
        int bin = 255;
        for (; bin > 0; bin--) {
            unsigned c = h[bin];
            if (cum + c >= kr) break;
            cum += c;
        }
        kr -= cum;
        unsigned pfx = g_prefix[s] | ((unsigned)bin << shift);
        g_prefix[s] = pfx;
        g_krem[s] = kr;
        if (round == 3) { g_kth[s] = pfx; g_needed[s] = kr; }
    }
}

// ------------------ compaction: exact top-k SET (ties -> lowest index) ------------------
__global__ __launch_bounds__(1024) void compact_kernel() {
    int n = blockIdx.x, lvl = blockIdx.y;
    int s = lvl * 2 + n;
    int L = c_L[lvl], k = c_k[lvl], lvl_off = lvl * 1000;
    unsigned kth = g_kth[s];
    int needed = (int)g_needed[s];
    int G = k - needed;
    const float* scp = g_scores + n * STOT + c_soff[lvl];
    const float4* bxp = g_boxes + n * STOT + c_soff[lvl];

    __shared__ unsigned wg[32], we[32];
    __shared__ int baseg, basee, totg, tote;
    if (threadIdx.x == 0) { baseg = 0; basee = 0; }
    __syncthreads();
    int lane = threadIdx.x & 31, w = threadIdx.x >> 5;

    for (int start = 0; start < L; start += 1024) {
        int i = start + threadIdx.x;
        bool gt = false, eq = false;
        float sc = 0.f;
        if (i < L) {
            sc = scp[i];
            unsigned key = f2key(sc);
            gt = key > kth;
            eq = (key == kth);
        }
        unsigned bg = __ballot_sync(0xffffffffu, gt);
        unsigned be = __ballot_sync(0xffffffffu, eq);
        if (lane == 0) { wg[w] = __popc(bg); we[w] = __popc(be); }
        __syncthreads();
        if (threadIdx.x < 32) {
            unsigned vg = wg[threadIdx.x], ve = we[threadIdx.x];
            unsigned ig = vg, ie = ve;
#pragma unroll
            for (int o = 1; o < 32; o <<= 1) {
                unsigned tg = __shfl_up_sync(0xffffffffu, ig, o);
                unsigned te = __shfl_up_sync(0xffffffffu, ie, o);
                if ((int)threadIdx.x >= o) { ig += tg; ie += te; }
            }
            wg[threadIdx.x] = ig - vg;
            we[threadIdx.x] = ie - ve;
            if (threadIdx.x == 31) { totg = (int)ig; tote = (int)ie; }
        }
        __syncthreads();
        if (gt) {
            int pos = baseg + (int)wg[w] + __popc(bg & ((1u << lane) - 1));
            g_cand_s[n * TCAND + lvl_off + pos] = sc;
            g_cand_b[n * TCAND + lvl_off + pos] = bxp[i];
        }
        if (eq) {
            int rank = basee + (int)we[w] + __popc(be & ((1u << lane) - 1));
            if (rank < needed) {
                int pos = G + rank;
                g_cand_s[n * TCAND + lvl_off + pos] = sc;
                g_cand_b[n * TCAND + lvl_off + pos] = bxp[i];
            }
        }
        __syncthreads();
        if (threadIdx.x == 0) { baseg += totg; basee += tote; }
        __syncthreads();
    }
}

// ------------------ per-image bitonic sort (score desc, idx asc) ------------------
__global__ __launch_bounds__(1024) void sort_kernel() {
    extern __shared__ unsigned long long keys[];
    int n = blockIdx.x;
    for (int i = threadIdx.x; i < 8192; i += 1024) {
        unsigned long long kk;
        if (i < TCAND) {
            unsigned sk = f2key(g_cand_s[n * TCAND + i]);
            kk = ((unsigned long long)(~sk) << 32) | (unsigned)i;
        } else kk = ~0ULL;
        keys[i] = kk;
    }
    for (int k = 2; k <= 8192; k <<= 1) {
        for (int j = k >> 1; j > 0; j >>= 1) {
            __syncthreads();
            for (int i = threadIdx.x; i < 8192; i += 1024) {
                int ixj = i ^ j;
                if (ixj > i) {
                    unsigned long long a = keys[i], b = keys[ixj];
                    bool up = ((i & k) == 0);
                    if ((a > b) == up) { keys[i] = b; keys[ixj] = a; }
                }
            }
        }
    }
    __syncthreads();
    for (int i = threadIdx.x; i < TCAND; i += 1024) {
        int j = (int)(unsigned)(keys[i] & 0xffffffffu);
        float s = g_cand_s[n * TCAND + j];
        float4 b = g_cand_b[n * TCAND + j];
        int lvl = (j < 4000) ? (j / 1000) : 4;
        float off = (float)lvl * 1025.0f;
        float4 ob = make_float4(b.x + off, b.y + off, b.z + off, b.w + off);
        g_sorted_s[n * TCAND + i] = s;
        g_sorted_b[n * TCAND + i] = b;
        g_sorted_ob[n * TCAND + i] = ob;
        int pos = (int)atomicAdd(&g_lcnt[n * 5 + lvl], 1u);
        g_llist[(n * 5 + lvl) * 1000 + pos] = i;
        bool valid = (b.z - b.x > 0.f) && (b.w - b.y > 0.f);
        unsigned bal = __ballot_sync(0xffffffffu, valid);
        if ((threadIdx.x & 31) == 0) g_validw[n * NWORDS + (i >> 5)] = bal;
    }
}

// ------------------ IoU: same-level pairs only (cross-level sup == false exactly) ------------------
// grid (4, 32, 10): z = n*5+lvl
__global__ __launch_bounds__(256) void iou_kernel() {
    int seg = blockIdx.z;
    int n = seg / 5, lvl = seg - n * 5;
    int kl = c_k[lvl];
    int i0 = blockIdx.y * 32;
    if (i0 >= kl) return;

    __shared__ int    ssl[32];
    __shared__ float4 sbx[32];
    __shared__ float  sar[32];
    if (threadIdx.x < 32) {
        int ie = i0 + threadIdx.x;
        if (ie < kl) {
            int sl = g_llist[seg * 1000 + ie];
            ssl[threadIdx.x] = sl;
            float4 b = g_sorted_ob[n * TCAND + sl];
            sbx[threadIdx.x] = b;
            sar[threadIdx.x] = (b.z - b.x) * (b.w - b.y);
        } else ssl[threadIdx.x] = -1;
    }
    __syncthreads();

    int je = blockIdx.x * 256 + threadIdx.x;
    if (je >= kl) return;
    int slj = g_llist[seg * 1000 + je];
    float4 bj = g_sorted_ob[n * TCAND + slj];
    float areaj = (bj.z - bj.x) * (bj.w - bj.y);

#pragma unroll 4
    for (int ii = 0; ii < 32; ii++) {
        int sli = ssl[ii];
        if (sli < 0) break;
        if (slj > sli) {
            float4 bi = sbx[ii];
            float areai = sar[ii];
            float ltx = fmaxf(bi.x, bj.x), lty = fmaxf(bi.y, bj.y);
            float rbx = fminf(bi.z, bj.z), rby = fminf(bi.w, bj.w);
            float iw = fmaxf(rbx - ltx, 0.f), ih = fmaxf(rby - lty, 0.f);
            float inter = iw * ih;
            float uni = areai + areaj - inter;
            float iou = (uni > 0.f) ? (inter / uni) : 0.f;
            if (iou > 0.7f)
                atomicOr(&g_mask[((size_t)n * TCAND + sli) * NWORDS + (slj >> 5)],
                         1u << (slj & 31));
        }
    }
}

// ------------------ sequential greedy scan + ordered emission (1 warp / image) ------------------
__global__ void nms_scan(float* __restrict__ out) {
    int n = blockIdx.x;
    int lane = threadIdx.x;
    unsigned keep[5];
#pragma unroll
    for (int q = 0; q < 5; q++) {
        int w = lane * 5 + q;
        keep[q] = (w < NWORDS) ? 0xFFFFFFFFu : 0u;
    }
    const unsigned* mask = g_mask + (size_t)n * TCAND * NWORDS;
    const int NCH = TCAND / 8;
    unsigned cur[8][5], nxt[8][5];
#pragma unroll
    for (int t = 0; t < 8; t++)
#pragma unroll
        for (int q = 0; q < 5; q++) {
            int w = lane * 5 + q;
            cur[t][q] = (w < NWORDS) ? mask[(size_t)t * NWORDS + w] : 0u;
        }
    for (int c = 0; c < NCH; c++) {
        if (c + 1 < NCH) {
            int base = (c + 1) * 8;
#pragma unroll
            for (int t = 0; t < 8; t++)
#pragma unroll
                for (int q = 0; q < 5; q++) {
                    int w = lane * 5 + q;
                    nxt[t][q] = (w < NWORDS) ? mask[(size_t)(base + t) * NWORDS + w] : 0u;
                }
        }
#pragma unroll
        for (int t = 0; t < 8; t++) {
            int i = c * 8 + t;
            int wi = i >> 5;
            int owner = wi / 5;
            int qi = wi - owner * 5;
            unsigned kw;
            switch (qi) {
                case 0: kw = keep[0]; break;
                case 1: kw = keep[1]; break;
                case 2: kw = keep[2]; break;
                case 3: kw = keep[3]; break;
                default: kw = keep[4]; break;
            }
            unsigned word = __shfl_sync(0xffffffffu, kw, owner);
            if ((word >> (i & 31)) & 1u) {
#pragma unroll
                for (int q = 0; q < 5; q++) keep[q] &= ~cur[t][q];
            }
        }
#pragma unroll
        for (int t = 0; t < 8; t++)
#pragma unroll
            for (int q = 0; q < 5; q++) cur[t][q] = nxt[t][q];
    }
#pragma unroll
    for (int q = 0; q < 5; q++) {
        int w = lane * 5 + q;
        if (w < NWORDS) keep[q] &= g_validw[n * NWORDS + w];
    }
    int mycnt = 0;
#pragma unroll
    for (int q = 0; q < 5; q++) mycnt += __popc(keep[q]);
    int incl = mycnt;
#pragma unroll
    for (int o = 1; o < 32; o <<= 1) {
        int t = __shfl_up_sync(0xffffffffu, incl, o);
        if (lane >= o) incl += t;
    }
    int nk = __shfl_sync(0xffffffffu, incl, 31);
    int run = incl - mycnt;
    float ninf = __int_as_float((int)0xff800000u);
    float* outS = out + 8000;
#pragma unroll
    for (int q = 0; q < 5; q++) {
        int w = lane * 5 + q;
        if (w >= NWORDS) continue;
        unsigned kwv = keep[q];
        for (int b = 0; b < 32; b++) {
            int i = w * 32 + b;
            int ones_before = run + __popc(kwv & ((1u << b) - 1));
            bool kept = (kwv >> b) & 1u;
            int pos = kept ? ones_before : (nk + (i - ones_before));
            if (pos < 1000) {
                float4 bx = g_sorted_b[n * TCAND + i];
                float* ob = out + ((size_t)n * 1000 + pos) * 4;
                ob[0] = bx.x; ob[1] = bx.y; ob[2] = bx.z; ob[3] = bx.w;
                outS[n * 1000 + pos] = kept ? g_sorted_s[n * TCAND + i] : ninf;
            }
        }
        run += __popc(kwv);
    }
}

// ------------------ launch ------------------
extern "C" void kernel_launch(void* const* d_in, const int* in_sizes, int n_in,
                              void* d_out, int out_size) {
    (void)in_sizes; (void)n_in; (void)out_size;
    Feats feats;
    for (int i = 0; i < 5; i++) feats.p[i] = (const float*)d_in[i];
    const float* w_conv  = (const float*)d_in[5];
    const float* b_conv  = (const float*)d_in[6];
    const float* w_obj   = (const float*)d_in[7];
    const float* b_obj   = (const float*)d_in[8];
    const float* w_delta = (const float*)d_in[9];
    const float* b_delta = (const float*)d_in[10];

    static const double sizesT[5] = {32.0, 64.0, 128.0, 256.0, 512.0};
    static const double ratios[3] = {0.5, 1.0, 2.0};
    AnchorP ap;
    for (int l = 0; l < 5; l++) {
        double area = sizesT[l] * sizesT[l];
        for (int a = 0; a < 3; a++) {
            double w = sqrt(area / ratios[a]);
            double h = w * ratios[a];
            ap.cw[l * 3 + a] = -w / 2.0;
            ap.ch[l * 3 + a] = -h / 2.0;
        }
    }

    cudaFuncSetAttribute(conv_head_all, cudaFuncAttributeMaxDynamicSharedMemorySize, CONV_SMEM_B);
    conv_head_all<<<dim3(1364, NIMG), 256, CONV_SMEM_B>>>(
        feats, w_conv, b_conv, w_obj, b_obj, w_delta, b_delta, ap);

    clear_mask<<<(MASKW / 4 + 1023) / 1024 + 1, 1024>>>();

    init_select<<<10, 256>>>();
    for (int r = 0; r < 4; r++) {
        hist_kernel<<<dim3(32, NIMG, 5), 256>>>(r);
        pick_kernel<<<10, 256>>>(r);
    }
    compact_kernel<<<dim3(NIMG, 5), 1024>>>();

    cudaFuncSetAttribute(sort_kernel, cudaFuncAttributeMaxDynamicSharedMemorySize, 65536);
    sort_kernel<<<NIMG, 1024, 65536>>>();
    iou_kernel<<<dim3(4, 32, 10), 256>>>();
    nms_scan<<<NIMG, 32>>>((float*)d_out);
}

// round 14
// speedup vs baseline: 1.2821x; 1.2821x over previous
#include <cuda_runtime.h>
#include <math.h>
#include <stdint.h>

#define NIMG   2
#define TCAND  4768
#define NWORDS 149
#define STOT   261888
#define SCALE_CLAMP 4.135166556742356f
#define MASKW  (NIMG * TCAND * NWORDS)

// ------------------ static device scratch ------------------
__device__ float    g_scores[NIMG * STOT];
__device__ float4   g_boxes [NIMG * STOT];
__device__ unsigned g_hist[10 * 256];
__device__ unsigned g_prefix[10];
__device__ unsigned g_krem[10];
__device__ unsigned g_kth[10];
__device__ unsigned g_needed[10];
__device__ unsigned g_lcnt[10];
__device__ int      g_llist[10 * 1000];
__device__ float    g_cand_s[NIMG * TCAND];
__device__ float4   g_cand_b[NIMG * TCAND];
__device__ float    g_sorted_s[NIMG * TCAND];
__device__ float4   g_sorted_b[NIMG * TCAND];
__device__ float4   g_sorted_ob[NIMG * TCAND];
__device__ unsigned g_validw[NIMG * NWORDS];
__device__ unsigned g_mask[MASKW];

// ------------------ level tables ------------------
__constant__ int   c_H[5]      = {256, 128, 64, 32, 16};
__constant__ int   c_HW[5]     = {65536, 16384, 4096, 1024, 256};
__constant__ float c_stride[5] = {4.f, 8.f, 16.f, 32.f, 64.f};
__constant__ int   c_soff[5]   = {0, 196608, 245760, 258048, 261120};
__constant__ int   c_L[5]      = {196608, 49152, 12288, 3072, 768};
__constant__ int   c_k[5]      = {1000, 1000, 1000, 1000, 768};

struct Feats { const float* p[5]; };
struct AnchorP { double cw[15]; double ch[15]; };

// ------------------ helpers ------------------
__device__ __forceinline__ unsigned f2key(float f) {
    unsigned u = __float_as_uint(f);
    return (u & 0x80000000u) ? ~u : (u | 0x80000000u);
}
__device__ __forceinline__ float clip1024(float v) { return fminf(fmaxf(v, 0.f), 1024.f); }
__device__ __forceinline__ void ffma2(unsigned long long& d, unsigned long long a, unsigned long long b) {
    asm("fma.rn.f32x2 %0, %1, %2, %0;" : "+l"(d) : "l"(a), "l"(b));
}
__device__ __forceinline__ unsigned long long dup2(float x) {
    unsigned long long r;
    asm("mov.b64 %0, {%1, %1};" : "=l"(r) : "f"(x));
    return r;
}
__device__ __forceinline__ float2 unpack2(unsigned long long v) {
    float2 r;
    asm("mov.b64 {%0, %1}, %2;" : "=f"(r.x), "=f"(r.y) : "l"(v));
    return r;
}

// smem layout (floats): R10 geometry
#define SM_BS 8192
#define SM_T  12288
#define SM_SW 45824
#define TSTRIDE 131
#define CONV_SMEM_B (49664 * 4)

// ------------------ fused FFMA2 conv3x3 + head (+anchor decode), R10 geometry ------------------
// block tile: 256 co x 128 px, thread tile 16 co x 8 px, BK=16.
// grid: x = 682 pixel-tiles (512,128,32,8,2), y = img
__global__ __launch_bounds__(256, 1) void conv_head_all(
    Feats feats, const float* __restrict__ wgt, const float* __restrict__ bias,
    const float* __restrict__ w_obj, const float* __restrict__ b_obj,
    const float* __restrict__ w_delta, const float* __restrict__ b_delta,
    AnchorP ap)
{
    extern __shared__ __align__(16) float sm[];
    float* As = sm;
    float* Bs = sm + SM_BS;
    float* T  = sm + SM_T;
    float* sw = sm + SM_SW;

    const int tid = threadIdx.x;
    const int tx = tid & 15, ty = tid >> 4;

    for (int i = tid; i < 15 * 256; i += 256) {
        int row = i >> 8, c = i & 255;
        sw[i] = (row < 3) ? w_obj[row * 256 + c] : w_delta[(row - 3) * 256 + c];
    }

    int bx = blockIdx.x;
    int lvl, pt;
    if      (bx < 512) { lvl = 0; pt = bx; }
    else if (bx < 640) { lvl = 1; pt = bx - 512; }
    else if (bx < 672) { lvl = 2; pt = bx - 640; }
    else if (bx < 680) { lvl = 3; pt = bx - 672; }
    else               { lvl = 4; pt = bx - 680; }
    const int W  = c_H[lvl];
    const int HW = c_HW[lvl];
    const int n  = blockIdx.y;
    const int p0 = pt * 128;
    const float* inN = feats.p[lvl] + (size_t)n * 256 * HW;

    unsigned long long acc2[8][8];
#pragma unroll
    for (int i = 0; i < 8; i++)
#pragma unroll
        for (int j = 0; j < 8; j++) acc2[i][j] = 0ULL;

    const int ppB  = tid & 127;
    const int kkB0 = (tid >> 7) * 8;
    const float* wrow = wgt + (size_t)tid * 2304;
    const int p   = p0 + ppB;
    const int y0p = p / W;
    const int x0p = p - y0p * W;

    float4 avq[4];
    float  bv[8];

#pragma unroll
    for (int r = 0; r < 4; r++)
        avq[r] = *reinterpret_cast<const float4*>(wrow + r * 4);
#pragma unroll
    for (int q = 0; q < 8; q++) {
        int k  = kkB0 + q;
        int ci = k / 9;
        int rr = k - ci * 9;
        int ky = rr / 3;
        int kx = rr - ky * 3;
        int yy = y0p + ky - 1;
        int xx = x0p + kx - 1;
        float v = 0.f;
        if ((unsigned)yy < (unsigned)W && (unsigned)xx < (unsigned)W)
            v = inN[(size_t)ci * HW + yy * W + xx];
        bv[q] = v;
    }
    {
#pragma unroll
        for (int r = 0; r < 4; r++) {
            float wv[4] = {avq[r].x, avq[r].y, avq[r].z, avq[r].w};
#pragma unroll
            for (int q = 0; q < 4; q++) As[(r * 4 + q) * 256 + tid] = wv[q];
        }
#pragma unroll
        for (int q = 0; q < 8; q++) Bs[(kkB0 + q) * 128 + ppB] = bv[q];
    }
    __syncthreads();

    for (int c0 = 0; c0 < 144; c0++) {
        const int s = c0 & 1;
        const bool more = (c0 + 1) < 144;
        if (more) {
            const float* w2 = wrow + (c0 + 1) * 16;
#pragma unroll
            for (int r = 0; r < 4; r++)
                avq[r] = *reinterpret_cast<const float4*>(w2 + r * 4);
#pragma unroll
            for (int q = 0; q < 8; q++) {
                int k  = (c0 + 1) * 16 + kkB0 + q;
                int ci = k / 9;
                int rr = k - ci * 9;
                int ky = rr / 3;
                int kx = rr - ky * 3;
                int yy = y0p + ky - 1;
                int xx = x0p + kx - 1;
                float v = 0.f;
                if ((unsigned)yy < (unsigned)W && (unsigned)xx < (unsigned)W)
                    v = inN[(size_t)ci * HW + yy * W + xx];
                bv[q] = v;
            }
        }
        const float* Ab = As + s * 16 * 256;
        const float* Bb = Bs + s * 16 * 128;
#pragma unroll
        for (int kk = 0; kk < 16; kk++) {
            unsigned long long a2[8];
#pragma unroll
            for (int q = 0; q < 4; q++) {
                ulonglong2 tt = *reinterpret_cast<const ulonglong2*>(&Ab[kk * 256 + ty * 16 + q * 4]);
                a2[2 * q] = tt.x; a2[2 * q + 1] = tt.y;
            }
            float4 bq0 = *reinterpret_cast<const float4*>(&Bb[kk * 128 + tx * 4]);
            float4 bq1 = *reinterpret_cast<const float4*>(&Bb[kk * 128 + 64 + tx * 4]);
            unsigned long long b2[8];
            b2[0] = dup2(bq0.x); b2[1] = dup2(bq0.y);
            b2[2] = dup2(bq0.z); b2[3] = dup2(bq0.w);
            b2[4] = dup2(bq1.x); b2[5] = dup2(bq1.y);
            b2[6] = dup2(bq1.z); b2[7] = dup2(bq1.w);
#pragma unroll
            for (int i = 0; i < 8; i++)
#pragma unroll
                for (int j = 0; j < 8; j++)
                    ffma2(acc2[i][j], a2[i], b2[j]);
        }
        if (more) {
            float* Ad = As + (s ^ 1) * 16 * 256;
            float* Bd = Bs + (s ^ 1) * 16 * 128;
#pragma unroll
            for (int r = 0; r < 4; r++) {
                float wv[4] = {avq[r].x, avq[r].y, avq[r].z, avq[r].w};
#pragma unroll
                for (int q = 0; q < 4; q++) Ad[(r * 4 + q) * 256 + tid] = wv[q];
            }
#pragma unroll
            for (int q = 0; q < 8; q++) Bd[(kkB0 + q) * 128 + ppB] = bv[q];
        }
        __syncthreads();
    }

#pragma unroll
    for (int i = 0; i < 8; i++) {
        int co = ty * 16 + 2 * i;
        float bb0 = bias[co], bb1 = bias[co + 1];
        float* t0 = T + (size_t)co * TSTRIDE;
        float* t1 = t0 + TSTRIDE;
#pragma unroll
        for (int j = 0; j < 8; j++) {
            float2 v = unpack2(acc2[i][j]);
            int px = (j < 4) ? (tx * 4 + j) : (64 + tx * 4 + (j - 4));
            t0[px] = fmaxf(v.x + bb0, 0.f);
            t1[px] = fmaxf(v.y + bb1, 0.f);
        }
    }
    __syncthreads();

    if (tid < 128) {
        const int px = tid;
        const int pg = p0 + px;
        float acc[15];
#pragma unroll
        for (int i = 0; i < 15; i++) acc[i] = 0.f;
        for (int c = 0; c < 256; c++) {
            float v = T[(size_t)c * TSTRIDE + px];
#pragma unroll
            for (int i = 0; i < 15; i++) acc[i] = fmaf(v, sw[i * 256 + c], acc[i]);
        }
        const float stride = c_stride[lvl];
        float gx = (float)(pg % W) * stride;
        float gy = (float)(pg / W) * stride;
#pragma unroll
        for (int a = 0; a < 3; a++) {
            float s  = acc[a] + b_obj[a];
            float dx = acc[3 + a * 4 + 0] + b_delta[a * 4 + 0];
            float dy = acc[3 + a * 4 + 1] + b_delta[a * 4 + 1];
            float dw = fminf(acc[3 + a * 4 + 2] + b_delta[a * 4 + 2], SCALE_CLAMP);
            float dh = fminf(acc[3 + a * 4 + 3] + b_delta[a * 4 + 3], SCALE_CLAMP);
            double CW = ap.cw[lvl * 3 + a], CH = ap.ch[lvl * 3 + a];
            float x0 = (float)((double)gx + CW);
            float x1 = (float)((double)gx - CW);
            float y0 = (float)((double)gy + CH);
            float y1 = (float)((double)gy - CH);
            float aw = x1 - x0, ah = y1 - y0;
            float acx = x0 + 0.5f * aw, acy = y0 + 0.5f * ah;
            float pcx = dx * aw + acx;
            float pcy = dy * ah + acy;
            float pw = expf(dw) * aw;
            float ph = expf(dh) * ah;
            float4 bx4;
            bx4.x = clip1024(pcx - 0.5f * pw);
            bx4.y = clip1024(pcy - 0.5f * ph);
            bx4.z = clip1024(pcx + 0.5f * pw);
            bx4.w = clip1024(pcy + 0.5f * ph);
            int idx = n * STOT + c_soff[lvl] + pg * 3 + a;
            g_scores[idx] = s;
            g_boxes[idx]  = bx4;
        }
    }
}

// ------------------ mask clear (replay determinism) ------------------
__global__ void clear_mask() {
    size_t i = (size_t)blockIdx.x * 1024 + threadIdx.x;
    if (i * 4 + 3 < MASKW)
        *reinterpret_cast<uint4*>(g_mask + i * 4) = make_uint4(0, 0, 0, 0);
    else
        for (size_t w = i * 4; w < MASKW; w++) g_mask[w] = 0;
}

// ------------------ level-parallel radix-select ------------------
__global__ void init_select() {
    int s = blockIdx.x;
    if (threadIdx.x == 0) { g_prefix[s] = 0; g_krem[s] = (unsigned)c_k[s >> 1]; g_lcnt[s] = 0; }
    g_hist[s * 256 + threadIdx.x] = 0;
}

__global__ void hist_kernel(int round) {
    __shared__ unsigned sh[256];
    int n = blockIdx.y, lvl = blockIdx.z;
    int s = lvl * 2 + n;
    sh[threadIdx.x] = 0;
    __syncthreads();
    unsigned pfx = g_prefix[s];
    int shift = 24 - 8 * round;
    unsigned maskhi = (round == 0) ? 0u : (0xFFFFFFFFu << (shift + 8));
    int L = c_L[lvl];
    const float* sc = g_scores + n * STOT + c_soff[lvl];
    for (int i = blockIdx.x * blockDim.x + threadIdx.x; i < L; i += gridDim.x * blockDim.x) {
        unsigned key = f2key(sc[i]);
        if (((key ^ pfx) & maskhi) == 0)
            atomicAdd(&sh[(key >> shift) & 255], 1u);
    }
    __syncthreads();
    if (sh[threadIdx.x]) atomicAdd(&g_hist[s * 256 + threadIdx.x], sh[threadIdx.x]);
}

__global__ void pick_kernel(int round) {
    int s = blockIdx.x;
    __shared__ unsigned h[256];
    h[threadIdx.x] = g_hist[s * 256 + threadIdx.x];
    __syncthreads();
    g_hist[s * 256 + threadIdx.x] = 0;
    if (threadIdx.x == 0) {
        int shift = 24 - 8 * round;
        unsigned kr = g_krem[s];
        unsigned cum = 0;
        int bin = 255;
        for (; bin > 0; bin--) {
            unsigned c = h[bin];
            if (cum + c >= kr) break;
            cum += c;
        }
        kr -= cum;
        unsigned pfx = g_prefix[s] | ((unsigned)bin << shift);
        g_prefix[s] = pfx;
        g_krem[s] = kr;
        if (round == 3) { g_kth[s] = pfx; g_needed[s] = kr; }
    }
}

// ------------------ compaction: exact top-k SET (ties -> lowest index) ------------------
__global__ __launch_bounds__(1024) void compact_kernel() {
    int n = blockIdx.x, lvl = blockIdx.y;
    int s = lvl * 2 + n;
    int L = c_L[lvl], k = c_k[lvl], lvl_off = lvl * 1000;
    unsigned kth = g_kth[s];
    int needed = (int)g_needed[s];
    int G = k - needed;
    const float* scp = g_scores + n * STOT + c_soff[lvl];
    const float4* bxp = g_boxes + n * STOT + c_soff[lvl];

    __shared__ unsigned wg[32], we[32];
    __shared__ int baseg, basee, totg, tote;
    if (threadIdx.x == 0) { baseg = 0; basee = 0; }
    __syncthreads();
    int lane = threadIdx.x & 31, w = threadIdx.x >> 5;

    for (int start = 0; start < L; start += 1024) {
        int i = start + threadIdx.x;
        bool gt = false, eq = false;
        float sc = 0.f;
        if (i < L) {
            sc = scp[i];
            unsigned key = f2key(sc);
            gt = key > kth;
            eq = (key == kth);
        }
        unsigned bg = __ballot_sync(0xffffffffu, gt);
        unsigned be = __ballot_sync(0xffffffffu, eq);
        if (lane == 0) { wg[w] = __popc(bg); we[w] = __popc(be); }
        __syncthreads();
        if (threadIdx.x < 32) {
            unsigned vg = wg[threadIdx.x], ve = we[threadIdx.x];
            unsigned ig = vg, ie = ve;
#pragma unroll
            for (int o = 1; o < 32; o <<= 1) {
                unsigned tg = __shfl_up_sync(0xffffffffu, ig, o);
                unsigned te = __shfl_up_sync(0xffffffffu, ie, o);
                if ((int)threadIdx.x >= o) { ig += tg; ie += te; }
            }
            wg[threadIdx.x] = ig - vg;
            we[threadIdx.x] = ie - ve;
            if (threadIdx.x == 31) { totg = (int)ig; tote = (int)ie; }
        }
        __syncthreads();
        if (gt) {
            int pos = baseg + (int)wg[w] + __popc(bg & ((1u << lane) - 1));
            g_cand_s[n * TCAND + lvl_off + pos] = sc;
            g_cand_b[n * TCAND + lvl_off + pos] = bxp[i];
        }
        if (eq) {
            int rank = basee + (int)we[w] + __popc(be & ((1u << lane) - 1));
            if (rank < needed) {
                int pos = G + rank;
                g_cand_s[n * TCAND + lvl_off + pos] = sc;
                g_cand_b[n * TCAND + lvl_off + pos] = bxp[i];
            }
        }
        __syncthreads();
        if (threadIdx.x == 0) { baseg += totg; basee += tote; }
        __syncthreads();
    }
}

// ------------------ per-image bitonic sort (score desc, idx asc) ------------------
__global__ __launch_bounds__(1024) void sort_kernel() {
    extern __shared__ unsigned long long keys[];
    int n = blockIdx.x;
    for (int i = threadIdx.x; i < 8192; i += 1024) {
        unsigned long long kk;
        if (i < TCAND) {
            unsigned sk = f2key(g_cand_s[n * TCAND + i]);
            kk = ((unsigned long long)(~sk) << 32) | (unsigned)i;
        } else kk = ~0ULL;
        keys[i] = kk;
    }
    for (int k = 2; k <= 8192; k <<= 1) {
        for (int j = k >> 1; j > 0; j >>= 1) {
            __syncthreads();
            for (int i = threadIdx.x; i < 8192; i += 1024) {
                int ixj = i ^ j;
                if (ixj > i) {
                    unsigned long long a = keys[i], b = keys[ixj];
                    bool up = ((i & k) == 0);
                    if ((a > b) == up) { keys[i] = b; keys[ixj] = a; }
                }
            }
        }
    }
    __syncthreads();
    for (int i = threadIdx.x; i < TCAND; i += 1024) {
        int j = (int)(unsigned)(keys[i] & 0xffffffffu);
        float s = g_cand_s[n * TCAND + j];
        float4 b = g_cand_b[n * TCAND + j];
        int lvl = (j < 4000) ? (j / 1000) : 4;
        float off = (float)lvl * 1025.0f;
        float4 ob = make_float4(b.x + off, b.y + off, b.z + off, b.w + off);
        g_sorted_s[n * TCAND + i] = s;
        g_sorted_b[n * TCAND + i] = b;
        g_sorted_ob[n * TCAND + i] = ob;
        int pos = (int)atomicAdd(&g_lcnt[n * 5 + lvl], 1u);
        g_llist[(n * 5 + lvl) * 1000 + pos] = i;
        bool valid = (b.z - b.x > 0.f) && (b.w - b.y > 0.f);
        unsigned bal = __ballot_sync(0xffffffffu, valid);
        if ((threadIdx.x & 31) == 0) g_validw[n * NWORDS + (i >> 5)] = bal;
    }
}

// ------------------ IoU: same-level pairs only (cross-level sup == false exactly) ------------------
// grid (4, 32, 10): z = n*5+lvl
__global__ __launch_bounds__(256) void iou_kernel() {
    int seg = blockIdx.z;
    int n = seg / 5, lvl = seg - n * 5;
    int kl = c_k[lvl];
    int i0 = blockIdx.y * 32;
    if (i0 >= kl) return;

    __shared__ int    ssl[32];
    __shared__ float4 sbx[32];
    __shared__ float  sar[32];
    if (threadIdx.x < 32) {
        int ie = i0 + threadIdx.x;
        if (ie < kl) {
            int sl = g_llist[seg * 1000 + ie];
            ssl[threadIdx.x] = sl;
            float4 b = g_sorted_ob[n * TCAND + sl];
            sbx[threadIdx.x] = b;
            sar[threadIdx.x] = (b.z - b.x) * (b.w - b.y);
        } else ssl[threadIdx.x] = -1;
    }
    __syncthreads();

    int je = blockIdx.x * 256 + threadIdx.x;
    if (je >= kl) return;
    int slj = g_llist[seg * 1000 + je];
    float4 bj = g_sorted_ob[n * TCAND + slj];
    float areaj = (bj.z - bj.x) * (bj.w - bj.y);

#pragma unroll 4
    for (int ii = 0; ii < 32; ii++) {
        int sli = ssl[ii];
        if (sli < 0) break;
        if (slj > sli) {
            float4 bi = sbx[ii];
            float areai = sar[ii];
            float ltx = fmaxf(bi.x, bj.x), lty = fmaxf(bi.y, bj.y);
            float rbx = fminf(bi.z, bj.z), rby = fminf(bi.w, bj.w);
            float iw = fmaxf(rbx - ltx, 0.f), ih = fmaxf(rby - lty, 0.f);
            float inter = iw * ih;
            float uni = areai + areaj - inter;
            float iou = (uni > 0.f) ? (inter / uni) : 0.f;
            if (iou > 0.7f)
                atomicOr(&g_mask[((size_t)n * TCAND + sli) * NWORDS + (slj >> 5)],
                         1u << (slj & 31));
        }
    }
}

// ------------------ sequential greedy scan + ordered emission (1 warp / image) ------------------
__global__ void nms_scan(float* __restrict__ out) {
    int n = blockIdx.x;
    int lane = threadIdx.x;
    unsigned keep[5];
#pragma unroll
    for (int q = 0; q < 5; q++) {
        int w = lane * 5 + q;
        keep[q] = (w < NWORDS) ? 0xFFFFFFFFu : 0u;
    }
    const unsigned* mask = g_mask + (size_t)n * TCAND * NWORDS;
    const int NCH = TCAND / 8;
    unsigned cur[8][5], nxt[8][5];
#pragma unroll
    for (int t = 0; t < 8; t++)
#pragma unroll
        for (int q = 0; q < 5; q++) {
            int w = lane * 5 + q;
            cur[t][q] = (w < NWORDS) ? mask[(size_t)t * NWORDS + w] : 0u;
        }
    for (int c = 0; c < NCH; c++) {
        if (c + 1 < NCH) {
            int base = (c + 1) * 8;
#pragma unroll
            for (int t = 0; t < 8; t++)
#pragma unroll
                for (int q = 0; q < 5; q++) {
                    int w = lane * 5 + q;
                    nxt[t][q] = (w < NWORDS) ? mask[(size_t)(base + t) * NWORDS + w] : 0u;
                }
        }
#pragma unroll
        for (int t = 0; t < 8; t++) {
            int i = c * 8 + t;
            int wi = i >> 5;
            int owner = wi / 5;
            int qi = wi - owner * 5;
            unsigned kw;
            switch (qi) {
                case 0: kw = keep[0]; break;
                case 1: kw = keep[1]; break;
                case 2: kw = keep[2]; break;
                case 3: kw = keep[3]; break;
                default: kw = keep[4]; break;
            }
            unsigned word = __shfl_sync(0xffffffffu, kw, owner);
            if ((word >> (i & 31)) & 1u) {
#pragma unroll
                for (int q = 0; q < 5; q++) keep[q] &= ~cur[t][q];
            }
        }
#pragma unroll
        for (int t = 0; t < 8; t++)
#pragma unroll
            for (int q = 0; q < 5; q++) cur[t][q] = nxt[t][q];
    }
#pragma unroll
    for (int q = 0; q < 5; q++) {
        int w = lane * 5 + q;
        if (w < NWORDS) keep[q] &= g_validw[n * NWORDS + w];
    }
    int mycnt = 0;
#pragma unroll
    for (int q = 0; q < 5; q++) mycnt += __popc(keep[q]);
    int incl = mycnt;
#pragma unroll
    for (int o = 1; o < 32; o <<= 1) {
        int t = __shfl_up_sync(0xffffffffu, incl, o);
        if (lane >= o) incl += t;
    }
    int nk = __shfl_sync(0xffffffffu, incl, 31);
    int run = incl - mycnt;
    float ninf = __int_as_float((int)0xff800000u);
    float* outS = out + 8000;
#pragma unroll
    for (int q = 0; q < 5; q++) {
        int w = lane * 5 + q;
        if (w >= NWORDS) continue;
        unsigned kwv = keep[q];
        for (int b = 0; b < 32; b++) {
            int i = w * 32 + b;
            int ones_before = run + __popc(kwv & ((1u << b) - 1));
            bool kept = (kwv >> b) & 1u;
            int pos = kept ? ones_before : (nk + (i - ones_before));
            if (pos < 1000) {
                float4 bx = g_sorted_b[n * TCAND + i];
                float* ob = out + ((size_t)n * 1000 + pos) * 4;
                ob[0] = bx.x; ob[1] = bx.y; ob[2] = bx.z; ob[3] = bx.w;
                outS[n * 1000 + pos] = kept ? g_sorted_s[n * TCAND + i] : ninf;
            }
        }
        run += __popc(kwv);
    }
}

// ------------------ launch ------------------
extern "C" void kernel_launch(void* const* d_in, const int* in_sizes, int n_in,
                              void* d_out, int out_size) {
    (void)in_sizes; (void)n_in; (void)out_size;
    Feats feats;
    for (int i = 0; i < 5; i++) feats.p[i] = (const float*)d_in[i];
    const float* w_conv  = (const float*)d_in[5];
    const float* b_conv  = (const float*)d_in[6];
    const float* w_obj   = (const float*)d_in[7];
    const float* b_obj   = (const float*)d_in[8];
    const float* w_delta = (const float*)d_in[9];
    const float* b_delta = (const float*)d_in[10];

    static const double sizesT[5] = {32.0, 64.0, 128.0, 256.0, 512.0};
    static const double ratios[3] = {0.5, 1.0, 2.0};
    AnchorP ap;
    for (int l = 0; l < 5; l++) {
        double area = sizesT[l] * sizesT[l];
        for (int a = 0; a < 3; a++) {
            double w = sqrt(area / ratios[a]);
            double h = w * ratios[a];
            ap.cw[l * 3 + a] = -w / 2.0;
            ap.ch[l * 3 + a] = -h / 2.0;
        }
    }

    cudaFuncSetAttribute(conv_head_all, cudaFuncAttributeMaxDynamicSharedMemorySize, CONV_SMEM_B);
    conv_head_all<<<dim3(682, NIMG), 256, CONV_SMEM_B>>>(
        feats, w_conv, b_conv, w_obj, b_obj, w_delta, b_delta, ap);

    clear_mask<<<(MASKW / 4 + 1023) / 1024 + 1, 1024>>>();

    init_select<<<10, 256>>>();
    for (int r = 0; r < 4; r++) {
        hist_kernel<<<dim3(32, NIMG, 5), 256>>>(r);
        pick_kernel<<<10, 256>>>(r);
    }
    compact_kernel<<<dim3(NIMG, 5), 1024>>>();

    cudaFuncSetAttribute(sort_kernel, cudaFuncAttributeMaxDynamicSharedMemorySize, 65536);
    sort_kernel<<<NIMG, 1024, 65536>>>();
    iou_kernel<<<dim3(4, 32, 10), 256>>>();
    nms_scan<<<NIMG, 32>>>((float*)d_out);
}

// round 15
// speedup vs baseline: 1.3256x; 1.0340x over previous
#include <cuda_runtime.h>
#include <math.h>
#include <stdint.h>

#define NIMG   2
#define TCAND  4768
#define NWORDS 149
#define STOT   261888
#define SCALE_CLAMP 4.135166556742356f
#define MASKW  (NIMG * TCAND * NWORDS)

// ------------------ static device scratch ------------------
__device__ float    g_scores[NIMG * STOT];
__device__ float4   g_boxes [NIMG * STOT];
__device__ unsigned g_hist[10 * 256];
__device__ unsigned g_prefix[10];
__device__ unsigned g_krem[10];
__device__ unsigned g_kth[10];
__device__ unsigned g_needed[10];
__device__ unsigned g_lcnt[10];
__device__ int      g_llist[10 * 1000];
__device__ float    g_cand_s[NIMG * TCAND];
__device__ float4   g_cand_b[NIMG * TCAND];
__device__ float    g_sorted_s[NIMG * TCAND];
__device__ float4   g_sorted_b[NIMG * TCAND];
__device__ float4   g_sorted_ob[NIMG * TCAND];
__device__ unsigned g_validw[NIMG * NWORDS];
__device__ unsigned g_mask[MASKW];

// ------------------ level tables ------------------
__constant__ int   c_H[5]      = {256, 128, 64, 32, 16};
__constant__ int   c_HW[5]     = {65536, 16384, 4096, 1024, 256};
__constant__ float c_stride[5] = {4.f, 8.f, 16.f, 32.f, 64.f};
__constant__ int   c_soff[5]   = {0, 196608, 245760, 258048, 261120};
__constant__ int   c_L[5]      = {196608, 49152, 12288, 3072, 768};
__constant__ int   c_k[5]      = {1000, 1000, 1000, 1000, 768};

struct Feats { const float* p[5]; };
struct AnchorP { double cw[15]; double ch[15]; };

// ------------------ helpers ------------------
__device__ __forceinline__ unsigned f2key(float f) {
    unsigned u = __float_as_uint(f);
    return (u & 0x80000000u) ? ~u : (u | 0x80000000u);
}
__device__ __forceinline__ float clip1024(float v) { return fminf(fmaxf(v, 0.f), 1024.f); }
__device__ __forceinline__ void ffma2(unsigned long long& d, unsigned long long a, unsigned long long b) {
    asm("fma.rn.f32x2 %0, %1, %2, %0;" : "+l"(d) : "l"(a), "l"(b));
}
__device__ __forceinline__ unsigned long long dup2(float x) {
    unsigned long long r;
    asm("mov.b64 %0, {%1, %1};" : "=l"(r) : "f"(x));
    return r;
}
__device__ __forceinline__ float2 unpack2(unsigned long long v) {
    float2 r;
    asm("mov.b64 {%0, %1}, %2;" : "=f"(r.x), "=f"(r.y) : "l"(v));
    return r;
}

// smem layout (floats), BK=32 with T aliasing As/Bs:
// mainloop:  As [2][32][256] @ 0      (16384)
//            Bs [2][32][128] @ 16384  (8192)    -> [0, 24576)
// epilogue:  T  [256][131]   @ 0      (33536)   (aliases As/Bs; used after last barrier)
// always:    sw [15][256]    @ 33536  (3840)    total 37376 floats = 149504 B
#define SM_BS 16384
#define SM_SW 33536
#define TSTRIDE 131
#define CONV_SMEM_B (37376 * 4)

// ------------------ fused FFMA2 conv3x3 + head (+anchor decode), BK=32 ------------------
// block tile: 256 co x 128 px, thread tile 16 co x 8 px.
// grid: x = 682 pixel-tiles (512,128,32,8,2), y = img
__global__ __launch_bounds__(256, 1) void conv_head_all(
    Feats feats, const float* __restrict__ wgt, const float* __restrict__ bias,
    const float* __restrict__ w_obj, const float* __restrict__ b_obj,
    const float* __restrict__ w_delta, const float* __restrict__ b_delta,
    AnchorP ap)
{
    extern __shared__ __align__(16) float sm[];
    float* As = sm;
    float* Bs = sm + SM_BS;
    float* T  = sm;                 // aliases As/Bs (epilogue only)
    float* sw = sm + SM_SW;

    const int tid = threadIdx.x;
    const int tx = tid & 15, ty = tid >> 4;

    for (int i = tid; i < 15 * 256; i += 256) {
        int row = i >> 8, c = i & 255;
        sw[i] = (row < 3) ? w_obj[row * 256 + c] : w_delta[(row - 3) * 256 + c];
    }

    int bx = blockIdx.x;
    int lvl, pt;
    if      (bx < 512) { lvl = 0; pt = bx; }
    else if (bx < 640) { lvl = 1; pt = bx - 512; }
    else if (bx < 672) { lvl = 2; pt = bx - 640; }
    else if (bx < 680) { lvl = 3; pt = bx - 672; }
    else               { lvl = 4; pt = bx - 680; }
    const int W  = c_H[lvl];
    const int HW = c_HW[lvl];
    const int n  = blockIdx.y;
    const int p0 = pt * 128;
    const float* inN = feats.p[lvl] + (size_t)n * 256 * HW;

    unsigned long long acc2[8][8];
#pragma unroll
    for (int i = 0; i < 8; i++)
#pragma unroll
        for (int j = 0; j < 8; j++) acc2[i][j] = 0ULL;

    const int ppB  = tid & 127;
    const int kkB0 = (tid >> 7) * 16;    // 0 or 16
    const float* wrow = wgt + (size_t)tid * 2304;
    const int p   = p0 + ppB;
    const int y0p = p / W;
    const int x0p = p - y0p * W;

    float4 avq[8];
    float  bv[16];

    // ---- prefetch chunk 0 ----
#pragma unroll
    for (int r = 0; r < 8; r++)
        avq[r] = *reinterpret_cast<const float4*>(wrow + r * 4);
#pragma unroll
    for (int q = 0; q < 16; q++) {
        int k  = kkB0 + q;
        int ci = k / 9;
        int rr = k - ci * 9;
        int ky = rr / 3;
        int kx = rr - ky * 3;
        int yy = y0p + ky - 1;
        int xx = x0p + kx - 1;
        float v = 0.f;
        if ((unsigned)yy < (unsigned)W && (unsigned)xx < (unsigned)W)
            v = inN[(size_t)ci * HW + yy * W + xx];
        bv[q] = v;
    }
    {
#pragma unroll
        for (int r = 0; r < 8; r++) {
            float wv[4] = {avq[r].x, avq[r].y, avq[r].z, avq[r].w};
#pragma unroll
            for (int q = 0; q < 4; q++) As[(r * 4 + q) * 256 + tid] = wv[q];
        }
#pragma unroll
        for (int q = 0; q < 16; q++) Bs[(kkB0 + q) * 128 + ppB] = bv[q];
    }
    __syncthreads();

    for (int c0 = 0; c0 < 72; c0++) {
        const int s = c0 & 1;
        const bool more = (c0 + 1) < 72;
        if (more) {
            const float* w2 = wrow + (c0 + 1) * 32;
#pragma unroll
            for (int r = 0; r < 8; r++)
                avq[r] = *reinterpret_cast<const float4*>(w2 + r * 4);
#pragma unroll
            for (int q = 0; q < 16; q++) {
                int k  = (c0 + 1) * 32 + kkB0 + q;
                int ci = k / 9;
                int rr = k - ci * 9;
                int ky = rr / 3;
                int kx = rr - ky * 3;
                int yy = y0p + ky - 1;
                int xx = x0p + kx - 1;
                float v = 0.f;
                if ((unsigned)yy < (unsigned)W && (unsigned)xx < (unsigned)W)
                    v = inN[(size_t)ci * HW + yy * W + xx];
                bv[q] = v;
            }
        }
        const float* Ab = As + s * 32 * 256;
        const float* Bb = Bs + s * 32 * 128;
#pragma unroll
        for (int kk = 0; kk < 32; kk++) {
            unsigned long long a2[8];
#pragma unroll
            for (int q = 0; q < 4; q++) {
                ulonglong2 tt = *reinterpret_cast<const ulonglong2*>(&Ab[kk * 256 + ty * 16 + q * 4]);
                a2[2 * q] = tt.x; a2[2 * q + 1] = tt.y;
            }
            float4 bq0 = *reinterpret_cast<const float4*>(&Bb[kk * 128 + tx * 4]);
            float4 bq1 = *reinterpret_cast<const float4*>(&Bb[kk * 128 + 64 + tx * 4]);
            unsigned long long b2[8];
            b2[0] = dup2(bq0.x); b2[1] = dup2(bq0.y);
            b2[2] = dup2(bq0.z); b2[3] = dup2(bq0.w);
            b2[4] = dup2(bq1.x); b2[5] = dup2(bq1.y);
            b2[6] = dup2(bq1.z); b2[7] = dup2(bq1.w);
#pragma unroll
            for (int i = 0; i < 8; i++)
#pragma unroll
                for (int j = 0; j < 8; j++)
                    ffma2(acc2[i][j], a2[i], b2[j]);
        }
        if (more) {
            float* Ad = As + (s ^ 1) * 32 * 256;
            float* Bd = Bs + (s ^ 1) * 32 * 128;
#pragma unroll
            for (int r = 0; r < 8; r++) {
                float wv[4] = {avq[r].x, avq[r].y, avq[r].z, avq[r].w};
#pragma unroll
                for (int q = 0; q < 4; q++) Ad[(r * 4 + q) * 256 + tid] = wv[q];
            }
#pragma unroll
            for (int q = 0; q < 16; q++) Bd[(kkB0 + q) * 128 + ppB] = bv[q];
        }
        __syncthreads();
    }

    // ---- epilogue: bias + relu -> T (aliases As/Bs; mainloop complete) ----
#pragma unroll
    for (int i = 0; i < 8; i++) {
        int co = ty * 16 + 2 * i;
        float bb0 = bias[co], bb1 = bias[co + 1];
        float* t0 = T + (size_t)co * TSTRIDE;
        float* t1 = t0 + TSTRIDE;
#pragma unroll
        for (int j = 0; j < 8; j++) {
            float2 v = unpack2(acc2[i][j]);
            int px = (j < 4) ? (tx * 4 + j) : (64 + tx * 4 + (j - 4));
            t0[px] = fmaxf(v.x + bb0, 0.f);
            t1[px] = fmaxf(v.y + bb1, 0.f);
        }
    }
    __syncthreads();

    if (tid < 128) {
        const int px = tid;
        const int pg = p0 + px;
        float acc[15];
#pragma unroll
        for (int i = 0; i < 15; i++) acc[i] = 0.f;
        for (int c = 0; c < 256; c++) {
            float v = T[(size_t)c * TSTRIDE + px];
#pragma unroll
            for (int i = 0; i < 15; i++) acc[i] = fmaf(v, sw[i * 256 + c], acc[i]);
        }
        const float stride = c_stride[lvl];
        float gx = (float)(pg % W) * stride;
        float gy = (float)(pg / W) * stride;
#pragma unroll
        for (int a = 0; a < 3; a++) {
            float s  = acc[a] + b_obj[a];
            float dx = acc[3 + a * 4 + 0] + b_delta[a * 4 + 0];
            float dy = acc[3 + a * 4 + 1] + b_delta[a * 4 + 1];
            float dw = fminf(acc[3 + a * 4 + 2] + b_delta[a * 4 + 2], SCALE_CLAMP);
            float dh = fminf(acc[3 + a * 4 + 3] + b_delta[a * 4 + 3], SCALE_CLAMP);
            double CW = ap.cw[lvl * 3 + a], CH = ap.ch[lvl * 3 + a];
            float x0 = (float)((double)gx + CW);
            float x1 = (float)((double)gx - CW);
            float y0 = (float)((double)gy + CH);
            float y1 = (float)((double)gy - CH);
            float aw = x1 - x0, ah = y1 - y0;
            float acx = x0 + 0.5f * aw, acy = y0 + 0.5f * ah;
            float pcx = dx * aw + acx;
            float pcy = dy * ah + acy;
            float pw = expf(dw) * aw;
            float ph = expf(dh) * ah;
            float4 bx4;
            bx4.x = clip1024(pcx - 0.5f * pw);
            bx4.y = clip1024(pcy - 0.5f * ph);
            bx4.z = clip1024(pcx + 0.5f * pw);
            bx4.w = clip1024(pcy + 0.5f * ph);
            int idx = n * STOT + c_soff[lvl] + pg * 3 + a;
            g_scores[idx] = s;
            g_boxes[idx]  = bx4;
        }
    }
}

// ------------------ mask clear, quarter at a time (also ncu launch-count padding) ------------------
__global__ void clear_mask_part(int part) {
    const int Q = (MASKW + 3) / 4;
    int lo = part * Q;
    int hi = min(lo + Q, MASKW);
    for (int i = lo + blockIdx.x * 1024 + threadIdx.x; i < hi; i += gridDim.x * 1024)
        g_mask[i] = 0u;
}

// ------------------ level-parallel radix-select ------------------
__global__ void init_select() {
    int s = blockIdx.x;
    if (threadIdx.x == 0) { g_prefix[s] = 0; g_krem[s] = (unsigned)c_k[s >> 1]; g_lcnt[s] = 0; }
    g_hist[s * 256 + threadIdx.x] = 0;
}

__global__ void hist_kernel(int round) {
    __shared__ unsigned sh[256];
    int n = blockIdx.y, lvl = blockIdx.z;
    int s = lvl * 2 + n;
    sh[threadIdx.x] = 0;
    __syncthreads();
    unsigned pfx = g_prefix[s];
    int shift = 24 - 8 * round;
    unsigned maskhi = (round == 0) ? 0u : (0xFFFFFFFFu << (shift + 8));
    int L = c_L[lvl];
    const float* sc = g_scores + n * STOT + c_soff[lvl];
    for (int i = blockIdx.x * blockDim.x + threadIdx.x; i < L; i += gridDim.x * blockDim.x) {
        unsigned key = f2key(sc[i]);
        if (((key ^ pfx) & maskhi) == 0)
            atomicAdd(&sh[(key >> shift) & 255], 1u);
    }
    __syncthreads();
    if (sh[threadIdx.x]) atomicAdd(&g_hist[s * 256 + threadIdx.x], sh[threadIdx.x]);
}

__global__ void pick_kernel(int round) {
    int s = blockIdx.x;
    __shared__ unsigned h[256];
    h[threadIdx.x] = g_hist[s * 256 + threadIdx.x];
    __syncthreads();
    g_hist[s * 256 + threadIdx.x] = 0;
    if (threadIdx.x == 0) {
        int shift = 24 - 8 * round;
        unsigned kr = g_krem[s];
        unsigned cum = 0;
        int bin = 255;
        for (; bin > 0; bin--) {
            unsigned c = h[bin];
            if (cum + c >= kr) break;
            cum += c;
        }
        kr -= cum;
        unsigned pfx = g_prefix[s] | ((unsigned)bin << shift);
        g_prefix[s] = pfx;
        g_krem[s] = kr;
        if (round == 3) { g_kth[s] = pfx; g_needed[s] = kr; }
    }
}

// ------------------ compaction: exact top-k SET (ties -> lowest index) ------------------
__global__ __launch_bounds__(1024) void compact_kernel() {
    int n = blockIdx.x, lvl = blockIdx.y;
    int s = lvl * 2 + n;
    int L = c_L[lvl], k = c_k[lvl], lvl_off = lvl * 1000;
    unsigned kth = g_kth[s];
    int needed = (int)g_needed[s];
    int G = k - needed;
    const float* scp = g_scores + n * STOT + c_soff[lvl];
    const float4* bxp = g_boxes + n * STOT + c_soff[lvl];

    __shared__ unsigned wg[32], we[32];
    __shared__ int baseg, basee, totg, tote;
    if (threadIdx.x == 0) { baseg = 0; basee = 0; }
    __syncthreads();
    int lane = threadIdx.x & 31, w = threadIdx.x >> 5;

    for (int start = 0; start < L; start += 1024) {
        int i = start + threadIdx.x;
        bool gt = false, eq = false;
        float sc = 0.f;
        if (i < L) {
            sc = scp[i];
            unsigned key = f2key(sc);
            gt = key > kth;
            eq = (key == kth);
        }
        unsigned bg = __ballot_sync(0xffffffffu, gt);
        unsigned be = __ballot_sync(0xffffffffu, eq);
        if (lane == 0) { wg[w] = __popc(bg); we[w] = __popc(be); }
        __syncthreads();
        if (threadIdx.x < 32) {
            unsigned vg = wg[threadIdx.x], ve = we[threadIdx.x];
            unsigned ig = vg, ie = ve;
#pragma unroll
            for (int o = 1; o < 32; o <<= 1) {
                unsigned tg = __shfl_up_sync(0xffffffffu, ig, o);
                unsigned te = __shfl_up_sync(0xffffffffu, ie, o);
                if ((int)threadIdx.x >= o) { ig += tg; ie += te; }
            }
            wg[threadIdx.x] = ig - vg;
            we[threadIdx.x] = ie - ve;
            if (threadIdx.x == 31) { totg = (int)ig; tote = (int)ie; }
        }
        __syncthreads();
        if (gt) {
            int pos = baseg + (int)wg[w] + __popc(bg & ((1u << lane) - 1));
            g_cand_s[n * TCAND + lvl_off + pos] = sc;
            g_cand_b[n * TCAND + lvl_off + pos] = bxp[i];
        }
        if (eq) {
            int rank = basee + (int)we[w] + __popc(be & ((1u << lane) - 1));
            if (rank < needed) {
                int pos = G + rank;
                g_cand_s[n * TCAND + lvl_off + pos] = sc;
                g_cand_b[n * TCAND + lvl_off + pos] = bxp[i];
            }
        }
        __syncthreads();
        if (threadIdx.x == 0) { baseg += totg; basee += tote; }
        __syncthreads();
    }
}

// ------------------ per-image bitonic sort (score desc, idx asc) ------------------
__global__ __launch_bounds__(1024) void sort_kernel() {
    extern __shared__ unsigned long long keys[];
    int n = blockIdx.x;
    for (int i = threadIdx.x; i < 8192; i += 1024) {
        unsigned long long kk;
        if (i < TCAND) {
            unsigned sk = f2key(g_cand_s[n * TCAND + i]);
            kk = ((unsigned long long)(~sk) << 32) | (unsigned)i;
        } else kk = ~0ULL;
        keys[i] = kk;
    }
    for (int k = 2; k <= 8192; k <<= 1) {
        for (int j = k >> 1; j > 0; j >>= 1) {
            __syncthreads();
            for (int i = threadIdx.x; i < 8192; i += 1024) {
                int ixj = i ^ j;
                if (ixj > i) {
                    unsigned long long a = keys[i], b = keys[ixj];
                    bool up = ((i & k) == 0);
                    if ((a > b) == up) { keys[i] = b; keys[ixj] = a; }
                }
            }
        }
    }
    __syncthreads();
    for (int i = threadIdx.x; i < TCAND; i += 1024) {
        int j = (int)(unsigned)(keys[i] & 0xffffffffu);
        float s = g_cand_s[n * TCAND + j];
        float4 b = g_cand_b[n * TCAND + j];
        int lvl = (j < 4000) ? (j / 1000) : 4;
        float off = (float)lvl * 1025.0f;
        float4 ob = make_float4(b.x + off, b.y + off, b.z + off, b.w + off);
        g_sorted_s[n * TCAND + i] = s;
        g_sorted_b[n * TCAND + i] = b;
        g_sorted_ob[n * TCAND + i] = ob;
        int pos = (int)atomicAdd(&g_lcnt[n * 5 + lvl], 1u);
        g_llist[(n * 5 + lvl) * 1000 + pos] = i;
        bool valid = (b.z - b.x > 0.f) && (b.w - b.y > 0.f);
        unsigned bal = __ballot_sync(0xffffffffu, valid);
        if ((threadIdx.x & 31) == 0) g_validw[n * NWORDS + (i >> 5)] = bal;
    }
}

// ------------------ IoU: same-level pairs only (cross-level sup == false exactly) ------------------
__global__ __launch_bounds__(256) void iou_kernel() {
    int seg = blockIdx.z;
    int n = seg / 5, lvl = seg - n * 5;
    int kl = c_k[lvl];
    int i0 = blockIdx.y * 32;
    if (i0 >= kl) return;

    __shared__ int    ssl[32];
    __shared__ float4 sbx[32];
    __shared__ float  sar[32];
    if (threadIdx.x < 32) {
        int ie = i0 + threadIdx.x;
        if (ie < kl) {
            int sl = g_llist[seg * 1000 + ie];
            ssl[threadIdx.x] = sl;
            float4 b = g_sorted_ob[n * TCAND + sl];
            sbx[threadIdx.x] = b;
            sar[threadIdx.x] = (b.z - b.x) * (b.w - b.y);
        } else ssl[threadIdx.x] = -1;
    }
    __syncthreads();

    int je = blockIdx.x * 256 + threadIdx.x;
    if (je >= kl) return;
    int slj = g_llist[seg * 1000 + je];
    float4 bj = g_sorted_ob[n * TCAND + slj];
    float areaj = (bj.z - bj.x) * (bj.w - bj.y);

#pragma unroll 4
    for (int ii = 0; ii < 32; ii++) {
        int sli = ssl[ii];
        if (sli < 0) break;
        if (slj > sli) {
            float4 bi = sbx[ii];
            float areai = sar[ii];
            float ltx = fmaxf(bi.x, bj.x), lty = fmaxf(bi.y, bj.y);
            float rbx = fminf(bi.z, bj.z), rby = fminf(bi.w, bj.w);
            float iw = fmaxf(rbx - ltx, 0.f), ih = fmaxf(rby - lty, 0.f);
            float inter = iw * ih;
            float uni = areai + areaj - inter;
            float iou = (uni > 0.f) ? (inter / uni) : 0.f;
            if (iou > 0.7f)
                atomicOr(&g_mask[((size_t)n * TCAND + sli) * NWORDS + (slj >> 5)],
                         1u << (slj & 31));
        }
    }
}

// ------------------ sequential greedy scan + ordered emission (1 warp / image) ------------------
__global__ void nms_scan(float* __restrict__ out) {
    int n = blockIdx.x;
    int lane = threadIdx.x;
    unsigned keep[5];
#pragma unroll
    for (int q = 0; q < 5; q++) {
        int w = lane * 5 + q;
        keep[q] = (w < NWORDS) ? 0xFFFFFFFFu : 0u;
    }
    const unsigned* mask = g_mask + (size_t)n * TCAND * NWORDS;
    const int NCH = TCAND / 8;
    unsigned cur[8][5], nxt[8][5];
#pragma unroll
    for (int t = 0; t < 8; t++)
#pragma unroll
        for (int q = 0; q < 5; q++) {
            int w = lane * 5 + q;
            cur[t][q] = (w < NWORDS) ? mask[(size_t)t * NWORDS + w] : 0u;
        }
    for (int c = 0; c < NCH; c++) {
        if (c + 1 < NCH) {
            int base = (c + 1) * 8;
#pragma unroll
            for (int t = 0; t < 8; t++)
#pragma unroll
                for (int q = 0; q < 5; q++) {
                    int w = lane * 5 + q;
                    nxt[t][q] = (w < NWORDS) ? mask[(size_t)(base + t) * NWORDS + w] : 0u;
                }
        }
#pragma unroll
        for (int t = 0; t < 8; t++) {
            int i = c * 8 + t;
            int wi = i >> 5;
            int owner = wi / 5;
            int qi = wi - owner * 5;
            unsigned kw;
            switch (qi) {
                case 0: kw = keep[0]; break;
                case 1: kw = keep[1]; break;
                case 2: kw = keep[2]; break;
                case 3: kw = keep[3]; break;
                default: kw = keep[4]; break;
            }
            unsigned word = __shfl_sync(0xffffffffu, kw, owner);
            if ((word >> (i & 31)) & 1u) {
#pragma unroll
                for (int q = 0; q < 5; q++) keep[q] &= ~cur[t][q];
            }
        }
#pragma unroll
        for (int t = 0; t < 8; t++)
#pragma unroll
            for (int q = 0; q < 5; q++) cur[t][q] = nxt[t][q];
    }
#pragma unroll
    for (int q = 0; q < 5; q++) {
        int w = lane * 5 + q;
        if (w < NWORDS) keep[q] &= g_validw[n * NWORDS + w];
    }
    int mycnt = 0;
#pragma unroll
    for (int q = 0; q < 5; q++) mycnt += __popc(keep[q]);
    int incl = mycnt;
#pragma unroll
    for (int o = 1; o < 32; o <<= 1) {
        int t = __shfl_up_sync(0xffffffffu, incl, o);
        if (lane >= o) incl += t;
    }
    int nk = __shfl_sync(0xffffffffu, incl, 31);
    int run = incl - mycnt;
    float ninf = __int_as_float((int)0xff800000u);
    float* outS = out + 8000;
#pragma unroll
    for (int q = 0; q < 5; q++) {
        int w = lane * 5 + q;
        if (w >= NWORDS) continue;
        unsigned kwv = keep[q];
        for (int b = 0; b < 32; b++) {
            int i = w * 32 + b;
            int ones_before = run + __popc(kwv & ((1u << b) - 1));
            bool kept = (kwv >> b) & 1u;
            int pos = kept ? ones_before : (nk + (i - ones_before));
            if (pos < 1000) {
                float4 bx = g_sorted_b[n * TCAND + i];
                float* ob = out + ((size_t)n * 1000 + pos) * 4;
                ob[0] = bx.x; ob[1] = bx.y; ob[2] = bx.z; ob[3] = bx.w;
                outS[n * 1000 + pos] = kept ? g_sorted_s[n * TCAND + i] : ninf;
            }
        }
        run += __popc(kwv);
    }
}

// ------------------ launch ------------------
extern "C" void kernel_launch(void* const* d_in, const int* in_sizes, int n_in,
                              void* d_out, int out_size) {
    (void)in_sizes; (void)n_in; (void)out_size;
    Feats feats;
    for (int i = 0; i < 5; i++) feats.p[i] = (const float*)d_in[i];
    const float* w_conv  = (const float*)d_in[5];
    const float* b_conv  = (const float*)d_in[6];
    const float* w_obj   = (const float*)d_in[7];
    const float* b_obj   = (const float*)d_in[8];
    const float* w_delta = (const float*)d_in[9];
    const float* b_delta = (const float*)d_in[10];

    static const double sizesT[5] = {32.0, 64.0, 128.0, 256.0, 512.0};
    static const double ratios[3] = {0.5, 1.0, 2.0};
    AnchorP ap;
    for (int l = 0; l < 5; l++) {
        double area = sizesT[l] * sizesT[l];
        for (int a = 0; a < 3; a++) {
            double w = sqrt(area / ratios[a]);
            double h = w * ratios[a];
            ap.cw[l * 3 + a] = -w / 2.0;
            ap.ch[l * 3 + a] = -h / 2.0;
        }
    }

    // launches 1-5: independent of conv (mask clear quarters + select init).
    // This also places conv_head_all at launch #6 where ncu (-s 5 -c 1) samples.
    for (int q = 0; q < 4; q++)
        clear_mask_part<<<96, 1024>>>(q);
    init_select<<<10, 256>>>();

    cudaFuncSetAttribute(conv_head_all, cudaFuncAttributeMaxDynamicSharedMemorySize, CONV_SMEM_B);
    conv_head_all<<<dim3(682, NIMG), 256, CONV_SMEM_B>>>(
        feats, w_conv, b_conv, w_obj, b_obj, w_delta, b_delta, ap);

    for (int r = 0; r < 4; r++) {
        hist_kernel<<<dim3(32, NIMG, 5), 256>>>(r);
        pick_kernel<<<10, 256>>>(r);
    }
    compact_kernel<<<dim3(NIMG, 5), 1024>>>();

    cudaFuncSetAttribute(sort_kernel, cudaFuncAttributeMaxDynamicSharedMemorySize, 65536);
    sort_kernel<<<NIMG, 1024, 65536>>>();
    iou_kernel<<<dim3(4, 32, 10), 256>>>();
    nms_scan<<<NIMG, 32>>>((float*)d_out);
}

// round 16
// speedup vs baseline: 1.4648x; 1.1050x over previous
#include <cuda_runtime.h>
#include <math.h>
#include <stdint.h>

#define NIMG   2
#define TCAND  4768
#define NWORDS 149
#define STOT   261888
#define SCALE_CLAMP 4.135166556742356f
#define LMASKW (10 * 1000 * 32)

// ------------------ static device scratch ------------------
__device__ float    g_scores[NIMG * STOT];
__device__ float4   g_boxes [NIMG * STOT];
__device__ unsigned g_hist[10 * 256];
__device__ unsigned g_prefix[10];
__device__ unsigned g_krem[10];
__device__ unsigned g_kth[10];
__device__ unsigned g_needed[10];
__device__ int      g_slvl[NIMG * TCAND];
__device__ int      g_llist[10 * 1000];
__device__ float    g_cand_s[NIMG * TCAND];
__device__ float4   g_cand_b[NIMG * TCAND];
__device__ float    g_sorted_s[NIMG * TCAND];
__device__ float4   g_sorted_b[NIMG * TCAND];
__device__ float4   g_sorted_ob[NIMG * TCAND];
__device__ unsigned g_validw[NIMG * NWORDS];
__device__ unsigned g_lmask[LMASKW];        // per-level suppression bits [seg][entry][32]
__device__ unsigned g_lkeepw[10 * 32];      // per-level keep words
__device__ unsigned g_keepw[NIMG * NWORDS]; // global keep words

// ------------------ level tables ------------------
__constant__ int   c_H[5]      = {256, 128, 64, 32, 16};
__constant__ int   c_HW[5]     = {65536, 16384, 4096, 1024, 256};
__constant__ float c_stride[5] = {4.f, 8.f, 16.f, 32.f, 64.f};
__constant__ int   c_soff[5]   = {0, 196608, 245760, 258048, 261120};
__constant__ int   c_L[5]      = {196608, 49152, 12288, 3072, 768};
__constant__ int   c_k[5]      = {1000, 1000, 1000, 1000, 768};

struct Feats { const float* p[5]; };
struct AnchorP { double cw[15]; double ch[15]; };

// ------------------ helpers ------------------
__device__ __forceinline__ unsigned f2key(float f) {
    unsigned u = __float_as_uint(f);
    return (u & 0x80000000u) ? ~u : (u | 0x80000000u);
}
__device__ __forceinline__ float clip1024(float v) { return fminf(fmaxf(v, 0.f), 1024.f); }
__device__ __forceinline__ void ffma2(unsigned long long& d, unsigned long long a, unsigned long long b) {
    asm("fma.rn.f32x2 %0, %1, %2, %0;" : "+l"(d) : "l"(a), "l"(b));
}
__device__ __forceinline__ unsigned long long dup2(float x) {
    unsigned long long r;
    asm("mov.b64 %0, {%1, %1};" : "=l"(r) : "f"(x));
    return r;
}
__device__ __forceinline__ float2 unpack2(unsigned long long v) {
    float2 r;
    asm("mov.b64 {%0, %1}, %2;" : "=f"(r.x), "=f"(r.y) : "l"(v));
    return r;
}

// smem layout (floats), BK=32 with T aliasing As/Bs (proven R15 geometry)
#define SM_BS 16384
#define SM_SW 33536
#define TSTRIDE 131
#define CONV_SMEM_B (37376 * 4)

// ------------------ fused FFMA2 conv3x3 + head (+anchor decode), BK=32 ------------------
__global__ __launch_bounds__(256, 1) void conv_head_all(
    Feats feats, const float* __restrict__ wgt, const float* __restrict__ bias,
    const float* __restrict__ w_obj, const float* __restrict__ b_obj,
    const float* __restrict__ w_delta, const float* __restrict__ b_delta,
    AnchorP ap)
{
    extern __shared__ __align__(16) float sm[];
    float* As = sm;
    float* Bs = sm + SM_BS;
    float* T  = sm;
    float* sw = sm + SM_SW;

    const int tid = threadIdx.x;
    const int tx = tid & 15, ty = tid >> 4;

    for (int i = tid; i < 15 * 256; i += 256) {
        int row = i >> 8, c = i & 255;
        sw[i] = (row < 3) ? w_obj[row * 256 + c] : w_delta[(row - 3) * 256 + c];
    }

    int bx = blockIdx.x;
    int lvl, pt;
    if      (bx < 512) { lvl = 0; pt = bx; }
    else if (bx < 640) { lvl = 1; pt = bx - 512; }
    else if (bx < 672) { lvl = 2; pt = bx - 640; }
    else if (bx < 680) { lvl = 3; pt = bx - 672; }
    else               { lvl = 4; pt = bx - 680; }
    const int W  = c_H[lvl];
    const int HW = c_HW[lvl];
    const int n  = blockIdx.y;
    const int p0 = pt * 128;
    const float* inN = feats.p[lvl] + (size_t)n * 256 * HW;

    unsigned long long acc2[8][8];
#pragma unroll
    for (int i = 0; i < 8; i++)
#pragma unroll
        for (int j = 0; j < 8; j++) acc2[i][j] = 0ULL;

    const int ppB  = tid & 127;
    const int kkB0 = (tid >> 7) * 16;
    const float* wrow = wgt + (size_t)tid * 2304;
    const int p   = p0 + ppB;
    const int y0p = p / W;
    const int x0p = p - y0p * W;

    float4 avq[8];
    float  bv[16];

#pragma unroll
    for (int r = 0; r < 8; r++)
        avq[r] = *reinterpret_cast<const float4*>(wrow + r * 4);
#pragma unroll
    for (int q = 0; q < 16; q++) {
        int k  = kkB0 + q;
        int ci = k / 9;
        int rr = k - ci * 9;
        int ky = rr / 3;
        int kx = rr - ky * 3;
        int yy = y0p + ky - 1;
        int xx = x0p + kx - 1;
        float v = 0.f;
        if ((unsigned)yy < (unsigned)W && (unsigned)xx < (unsigned)W)
            v = inN[(size_t)ci * HW + yy * W + xx];
        bv[q] = v;
    }
    {
#pragma unroll
        for (int r = 0; r < 8; r++) {
            float wv[4] = {avq[r].x, avq[r].y, avq[r].z, avq[r].w};
#pragma unroll
            for (int q = 0; q < 4; q++) As[(r * 4 + q) * 256 + tid] = wv[q];
        }
#pragma unroll
        for (int q = 0; q < 16; q++) Bs[(kkB0 + q) * 128 + ppB] = bv[q];
    }
    __syncthreads();

    for (int c0 = 0; c0 < 72; c0++) {
        const int s = c0 & 1;
        const bool more = (c0 + 1) < 72;
        if (more) {
            const float* w2 = wrow + (c0 + 1) * 32;
#pragma unroll
            for (int r = 0; r < 8; r++)
                avq[r] = *reinterpret_cast<const float4*>(w2 + r * 4);
#pragma unroll
            for (int q = 0; q < 16; q++) {
                int k  = (c0 + 1) * 32 + kkB0 + q;
                int ci = k / 9;
                int rr = k - ci * 9;
                int ky = rr / 3;
                int kx = rr - ky * 3;
                int yy = y0p + ky - 1;
                int xx = x0p + kx - 1;
                float v = 0.f;
                if ((unsigned)yy < (unsigned)W && (unsigned)xx < (unsigned)W)
                    v = inN[(size_t)ci * HW + yy * W + xx];
                bv[q] = v;
            }
        }
        const float* Ab = As + s * 32 * 256;
        const float* Bb = Bs + s * 32 * 128;
#pragma unroll
        for (int kk = 0; kk < 32; kk++) {
            unsigned long long a2[8];
#pragma unroll
            for (int q = 0; q < 4; q++) {
                ulonglong2 tt = *reinterpret_cast<const ulonglong2*>(&Ab[kk * 256 + ty * 16 + q * 4]);
                a2[2 * q] = tt.x; a2[2 * q + 1] = tt.y;
            }
            float4 bq0 = *reinterpret_cast<const float4*>(&Bb[kk * 128 + tx * 4]);
            float4 bq1 = *reinterpret_cast<const float4*>(&Bb[kk * 128 + 64 + tx * 4]);
            unsigned long long b2[8];
            b2[0] = dup2(bq0.x); b2[1] = dup2(bq0.y);
            b2[2] = dup2(bq0.z); b2[3] = dup2(bq0.w);
            b2[4] = dup2(bq1.x); b2[5] = dup2(bq1.y);
            b2[6] = dup2(bq1.z); b2[7] = dup2(bq1.w);
#pragma unroll
            for (int i = 0; i < 8; i++)
#pragma unroll
                for (int j = 0; j < 8; j++)
                    ffma2(acc2[i][j], a2[i], b2[j]);
        }
        if (more) {
            float* Ad = As + (s ^ 1) * 32 * 256;
            float* Bd = Bs + (s ^ 1) * 32 * 128;
#pragma unroll
            for (int r = 0; r < 8; r++) {
                float wv[4] = {avq[r].x, avq[r].y, avq[r].z, avq[r].w};
#pragma unroll
                for (int q = 0; q < 4; q++) Ad[(r * 4 + q) * 256 + tid] = wv[q];
            }
#pragma unroll
            for (int q = 0; q < 16; q++) Bd[(kkB0 + q) * 128 + ppB] = bv[q];
        }
        __syncthreads();
    }

#pragma unroll
    for (int i = 0; i < 8; i++) {
        int co = ty * 16 + 2 * i;
        float bb0 = bias[co], bb1 = bias[co + 1];
        float* t0 = T + (size_t)co * TSTRIDE;
        float* t1 = t0 + TSTRIDE;
#pragma unroll
        for (int j = 0; j < 8; j++) {
            float2 v = unpack2(acc2[i][j]);
            int px = (j < 4) ? (tx * 4 + j) : (64 + tx * 4 + (j - 4));
            t0[px] = fmaxf(v.x + bb0, 0.f);
            t1[px] = fmaxf(v.y + bb1, 0.f);
        }
    }
    __syncthreads();

    if (tid < 128) {
        const int px = tid;
        const int pg = p0 + px;
        float acc[15];
#pragma unroll
        for (int i = 0; i < 15; i++) acc[i] = 0.f;
        for (int c = 0; c < 256; c++) {
            float v = T[(size_t)c * TSTRIDE + px];
#pragma unroll
            for (int i = 0; i < 15; i++) acc[i] = fmaf(v, sw[i * 256 + c], acc[i]);
        }
        const float stride = c_stride[lvl];
        float gx = (float)(pg % W) * stride;
        float gy = (float)(pg / W) * stride;
#pragma unroll
        for (int a = 0; a < 3; a++) {
            float s  = acc[a] + b_obj[a];
            float dx = acc[3 + a * 4 + 0] + b_delta[a * 4 + 0];
            float dy = acc[3 + a * 4 + 1] + b_delta[a * 4 + 1];
            float dw = fminf(acc[3 + a * 4 + 2] + b_delta[a * 4 + 2], SCALE_CLAMP);
            float dh = fminf(acc[3 + a * 4 + 3] + b_delta[a * 4 + 3], SCALE_CLAMP);
            double CW = ap.cw[lvl * 3 + a], CH = ap.ch[lvl * 3 + a];
            float x0 = (float)((double)gx + CW);
            float x1 = (float)((double)gx - CW);
            float y0 = (float)((double)gy + CH);
            float y1 = (float)((double)gy - CH);
            float aw = x1 - x0, ah = y1 - y0;
            float acx = x0 + 0.5f * aw, acy = y0 + 0.5f * ah;
            float pcx = dx * aw + acx;
            float pcy = dy * ah + acy;
            float pw = expf(dw) * aw;
            float ph = expf(dh) * ah;
            float4 bx4;
            bx4.x = clip1024(pcx - 0.5f * pw);
            bx4.y = clip1024(pcy - 0.5f * ph);
            bx4.z = clip1024(pcx + 0.5f * pw);
            bx4.w = clip1024(pcy + 0.5f * ph);
            int idx = n * STOT + c_soff[lvl] + pg * 3 + a;
            g_scores[idx] = s;
            g_boxes[idx]  = bx4;
        }
    }
}

// ------------------ clear per-level mask + global keep words ------------------
__global__ void clear_aux() {
    int i = blockIdx.x * 1024 + threadIdx.x;
    for (int w = i; w < LMASKW; w += gridDim.x * 1024) g_lmask[w] = 0u;
    if (i < NIMG * NWORDS) g_keepw[i] = 0u;
}

// ------------------ level-parallel radix-select ------------------
__global__ void init_select() {
    int s = blockIdx.x;
    if (threadIdx.x == 0) { g_prefix[s] = 0; g_krem[s] = (unsigned)c_k[s >> 1]; }
    g_hist[s * 256 + threadIdx.x] = 0;
}

__global__ void hist_kernel(int round) {
    __shared__ unsigned sh[256];
    int n = blockIdx.y, lvl = blockIdx.z;
    int s = lvl * 2 + n;
    sh[threadIdx.x] = 0;
    __syncthreads();
    unsigned pfx = g_prefix[s];
    int shift = 24 - 8 * round;
    unsigned maskhi = (round == 0) ? 0u : (0xFFFFFFFFu << (shift + 8));
    int L = c_L[lvl];
    const float* sc = g_scores + n * STOT + c_soff[lvl];
    for (int i = blockIdx.x * blockDim.x + threadIdx.x; i < L; i += gridDim.x * blockDim.x) {
        unsigned key = f2key(sc[i]);
        if (((key ^ pfx) & maskhi) == 0)
            atomicAdd(&sh[(key >> shift) & 255], 1u);
    }
    __syncthreads();
    if (sh[threadIdx.x]) atomicAdd(&g_hist[s * 256 + threadIdx.x], sh[threadIdx.x]);
}

__global__ void pick_kernel(int round) {
    int s = blockIdx.x;
    __shared__ unsigned h[256];
    h[threadIdx.x] = g_hist[s * 256 + threadIdx.x];
    __syncthreads();
    g_hist[s * 256 + threadIdx.x] = 0;
    if (threadIdx.x == 0) {
        int shift = 24 - 8 * round;
        unsigned kr = g_krem[s];
        unsigned cum = 0;
        int bin = 255;
        for (; bin > 0; bin--) {
            unsigned c = h[bin];
            if (cum + c >= kr) break;
            cum += c;
        }
        kr -= cum;
        unsigned pfx = g_prefix[s] | ((unsigned)bin << shift);
        g_prefix[s] = pfx;
        g_krem[s] = kr;
        if (round == 3) { g_kth[s] = pfx; g_needed[s] = kr; }
    }
}

// ------------------ compaction: exact top-k SET (ties -> lowest index) ------------------
__global__ __launch_bounds__(1024) void compact_kernel() {
    int n = blockIdx.x, lvl = blockIdx.y;
    int s = lvl * 2 + n;
    int L = c_L[lvl], k = c_k[lvl], lvl_off = lvl * 1000;
    unsigned kth = g_kth[s];
    int needed = (int)g_needed[s];
    int G = k - needed;
    const float* scp = g_scores + n * STOT + c_soff[lvl];
    const float4* bxp = g_boxes + n * STOT + c_soff[lvl];

    __shared__ unsigned wg[32], we[32];
    __shared__ int baseg, basee, totg, tote;
    if (threadIdx.x == 0) { baseg = 0; basee = 0; }
    __syncthreads();
    int lane = threadIdx.x & 31, w = threadIdx.x >> 5;

    for (int start = 0; start < L; start += 1024) {
        int i = start + threadIdx.x;
        bool gt = false, eq = false;
        float sc = 0.f;
        if (i < L) {
            sc = scp[i];
            unsigned key = f2key(sc);
            gt = key > kth;
            eq = (key == kth);
        }
        unsigned bg = __ballot_sync(0xffffffffu, gt);
        unsigned be = __ballot_sync(0xffffffffu, eq);
        if (lane == 0) { wg[w] = __popc(bg); we[w] = __popc(be); }
        __syncthreads();
        if (threadIdx.x < 32) {
            unsigned vg = wg[threadIdx.x], ve = we[threadIdx.x];
            unsigned ig = vg, ie = ve;
#pragma unroll
            for (int o = 1; o < 32; o <<= 1) {
                unsigned tg = __shfl_up_sync(0xffffffffu, ig, o);
                unsigned te = __shfl_up_sync(0xffffffffu, ie, o);
                if ((int)threadIdx.x >= o) { ig += tg; ie += te; }
            }
            wg[threadIdx.x] = ig - vg;
            we[threadIdx.x] = ie - ve;
            if (threadIdx.x == 31) { totg = (int)ig; tote = (int)ie; }
        }
        __syncthreads();
        if (gt) {
            int pos = baseg + (int)wg[w] + __popc(bg & ((1u << lane) - 1));
            g_cand_s[n * TCAND + lvl_off + pos] = sc;
            g_cand_b[n * TCAND + lvl_off + pos] = bxp[i];
        }
        if (eq) {
            int rank = basee + (int)we[w] + __popc(be & ((1u << lane) - 1));
            if (rank < needed) {
                int pos = G + rank;
                g_cand_s[n * TCAND + lvl_off + pos] = sc;
                g_cand_b[n * TCAND + lvl_off + pos] = bxp[i];
            }
        }
        __syncthreads();
        if (threadIdx.x == 0) { baseg += totg; basee += tote; }
        __syncthreads();
    }
}

// ------------------ per-image bitonic sort (score desc, idx asc) ------------------
__global__ __launch_bounds__(1024) void sort_kernel() {
    extern __shared__ unsigned long long keys[];
    int n = blockIdx.x;
    for (int i = threadIdx.x; i < 8192; i += 1024) {
        unsigned long long kk;
        if (i < TCAND) {
            unsigned sk = f2key(g_cand_s[n * TCAND + i]);
            kk = ((unsigned long long)(~sk) << 32) | (unsigned)i;
        } else kk = ~0ULL;
        keys[i] = kk;
    }
    for (int k = 2; k <= 8192; k <<= 1) {
        for (int j = k >> 1; j > 0; j >>= 1) {
            __syncthreads();
            for (int i = threadIdx.x; i < 8192; i += 1024) {
                int ixj = i ^ j;
                if (ixj > i) {
                    unsigned long long a = keys[i], b = keys[ixj];
                    bool up = ((i & k) == 0);
                    if ((a > b) == up) { keys[i] = b; keys[ixj] = a; }
                }
            }
        }
    }
    __syncthreads();
    for (int i = threadIdx.x; i < TCAND; i += 1024) {
        int j = (int)(unsigned)(keys[i] & 0xffffffffu);
        float s = g_cand_s[n * TCAND + j];
        float4 b = g_cand_b[n * TCAND + j];
        int lvl = (j < 4000) ? (j / 1000) : 4;
        float off = (float)lvl * 1025.0f;
        float4 ob = make_float4(b.x + off, b.y + off, b.z + off, b.w + off);
        g_sorted_s[n * TCAND + i] = s;
        g_sorted_b[n * TCAND + i] = b;
        g_sorted_ob[n * TCAND + i] = ob;
        g_slvl[n * TCAND + i] = lvl;
        bool valid = (b.z - b.x > 0.f) && (b.w - b.y > 0.f);
        unsigned bal = __ballot_sync(0xffffffffu, valid);
        if ((threadIdx.x & 31) == 0) g_validw[n * NWORDS + (i >> 5)] = bal;
    }
}

// ------------------ build per-level slot lists, slot-ascending (deterministic) ------------------
__global__ __launch_bounds__(1024) void build_llist() {
    int seg = blockIdx.x;          // n*5+lvl
    int n = seg / 5, lvl = seg - n * 5;
    __shared__ unsigned wc[32];
    __shared__ int basep, tot;
    if (threadIdx.x == 0) basep = 0;
    __syncthreads();
    int lane = threadIdx.x & 31, w = threadIdx.x >> 5;
    for (int start = 0; start < TCAND; start += 1024) {
        int i = start + threadIdx.x;
        bool pred = (i < TCAND) && (g_slvl[n * TCAND + i] == lvl);
        unsigned bal = __ballot_sync(0xffffffffu, pred);
        if (lane == 0) wc[w] = __popc(bal);
        __syncthreads();
        if (threadIdx.x < 32) {
            unsigned v = wc[threadIdx.x];
            unsigned ig = v;
#pragma unroll
            for (int o = 1; o < 32; o <<= 1) {
                unsigned t = __shfl_up_sync(0xffffffffu, ig, o);
                if ((int)threadIdx.x >= o) ig += t;
            }
            wc[threadIdx.x] = ig - v;
            if (threadIdx.x == 31) tot = (int)ig;
        }
        __syncthreads();
        if (pred) {
            int pos = basep + (int)wc[w] + __popc(bal & ((1u << lane) - 1));
            g_llist[seg * 1000 + pos] = i;
        }
        __syncthreads();
        if (threadIdx.x == 0) basep += tot;
        __syncthreads();
    }
}

// ------------------ IoU: same-level pairs, per-level mask (je > ie) ------------------
// grid (4, 32, 10)
__global__ __launch_bounds__(256) void iou_kernel() {
    int seg = blockIdx.z;
    int n = seg / 5, lvl = seg % 5;
    int kl = c_k[lvl];
    int i0 = blockIdx.y * 32;
    if (i0 >= kl) return;

    __shared__ float4 sbx[32];
    __shared__ float  sar[32];
    if (threadIdx.x < 32) {
        int ie = i0 + threadIdx.x;
        if (ie < kl) {
            int sl = g_llist[seg * 1000 + ie];
            float4 b = g_sorted_ob[n * TCAND + sl];
            sbx[threadIdx.x] = b;
            sar[threadIdx.x] = (b.z - b.x) * (b.w - b.y);
        }
    }
    __syncthreads();

    int je = blockIdx.x * 256 + threadIdx.x;
    if (je >= kl || je <= i0) return;
    int slj = g_llist[seg * 1000 + je];
    float4 bj = g_sorted_ob[n * TCAND + slj];
    float areaj = (bj.z - bj.x) * (bj.w - bj.y);

#pragma unroll 4
    for (int ii = 0; ii < 32; ii++) {
        int ie = i0 + ii;
        if (ie >= kl) break;
        if (je > ie) {
            float4 bi = sbx[ii];
            float areai = sar[ii];
            float ltx = fmaxf(bi.x, bj.x), lty = fmaxf(bi.y, bj.y);
            float rbx = fminf(bi.z, bj.z), rby = fminf(bi.w, bj.w);
            float iw = fmaxf(rbx - ltx, 0.f), ih = fmaxf(rby - lty, 0.f);
            float inter = iw * ih;
            float uni = areai + areaj - inter;
            float iou = (uni > 0.f) ? (inter / uni) : 0.f;
            if (iou > 0.7f)
                atomicOr(&g_lmask[((size_t)seg * 1000 + ie) * 32 + (je >> 5)],
                         1u << (je & 31));
        }
    }
}

// ------------------ per-level greedy scan (10 parallel warps) ------------------
__global__ void nms_lvl() {
    int seg = blockIdx.x;
    int lvl = seg % 5;
    int kl = c_k[lvl];
    int lane = threadIdx.x;
    // init keep: bit set for entries < kl
    int lo = lane * 32;
    unsigned keep;
    if (kl >= lo + 32) keep = 0xFFFFFFFFu;
    else if (kl > lo)  keep = (1u << (kl - lo)) - 1u;
    else               keep = 0u;

    unsigned cur = g_lmask[((size_t)seg * 1000 + 0) * 32 + lane];
    for (int e = 0; e < kl; e++) {
        unsigned nxt = (e + 1 < kl) ? g_lmask[((size_t)seg * 1000 + e + 1) * 32 + lane] : 0u;
        int owner = e >> 5;
        unsigned kw = __shfl_sync(0xffffffffu, keep, owner);
        if ((kw >> (e & 31)) & 1u)
            keep &= ~cur;
        cur = nxt;
    }
    g_lkeepw[seg * 32 + lane] = keep;
}

// ------------------ map per-level keep back to global slot keep words ------------------
__global__ __launch_bounds__(1024) void map_keep() {
    int seg = blockIdx.x;
    int lvl = seg % 5;
    int n = seg / 5;
    int kl = c_k[lvl];
    for (int e = threadIdx.x; e < kl; e += 1024) {
        if ((g_lkeepw[seg * 32 + (e >> 5)] >> (e & 31)) & 1u) {
            int slot = g_llist[seg * 1000 + e];
            atomicOr(&g_keepw[n * NWORDS + (slot >> 5)], 1u << (slot & 31));
        }
    }
}

// ------------------ ordered emission (1 warp / image) ------------------
__global__ void nms_emit(float* __restrict__ out) {
    int n = blockIdx.x;
    int lane = threadIdx.x;
    unsigned keep[5];
#pragma unroll
    for (int q = 0; q < 5; q++) {
        int w = lane * 5 + q;
        keep[q] = (w < NWORDS) ? (g_keepw[n * NWORDS + w] & g_validw[n * NWORDS + w]) : 0u;
    }
    int mycnt = 0;
#pragma unroll
    for (int q = 0; q < 5; q++) mycnt += __popc(keep[q]);
    int incl = mycnt;
#pragma unroll
    for (int o = 1; o < 32; o <<= 1) {
        int t = __shfl_up_sync(0xffffffffu, incl, o);
        if (lane >= o) incl += t;
    }
    int nk = __shfl_sync(0xffffffffu, incl, 31);
    int run = incl - mycnt;
    float ninf = __int_as_float((int)0xff800000u);
    float* outS = out + 8000;
#pragma unroll
    for (int q = 0; q < 5; q++) {
        int w = lane * 5 + q;
        if (w >= NWORDS) continue;
        unsigned kwv = keep[q];
        for (int b = 0; b < 32; b++) {
            int i = w * 32 + b;
            int ones_before = run + __popc(kwv & ((1u << b) - 1));
            bool kept = (kwv >> b) & 1u;
            int pos = kept ? ones_before : (nk + (i - ones_before));
            if (pos < 1000) {
                float4 bx = g_sorted_b[n * TCAND + i];
                float* ob = out + ((size_t)n * 1000 + pos) * 4;
                ob[0] = bx.x; ob[1] = bx.y; ob[2] = bx.z; ob[3] = bx.w;
                outS[n * 1000 + pos] = kept ? g_sorted_s[n * TCAND + i] : ninf;
            }
        }
        run += __popc(kwv);
    }
}

// ------------------ launch ------------------
extern "C" void kernel_launch(void* const* d_in, const int* in_sizes, int n_in,
                              void* d_out, int out_size) {
    (void)in_sizes; (void)n_in; (void)out_size;
    Feats feats;
    for (int i = 0; i < 5; i++) feats.p[i] = (const float*)d_in[i];
    const float* w_conv  = (const float*)d_in[5];
    const float* b_conv  = (const float*)d_in[6];
    const float* w_obj   = (const float*)d_in[7];
    const float* b_obj   = (const float*)d_in[8];
    const float* w_delta = (const float*)d_in[9];
    const float* b_delta = (const float*)d_in[10];

    static const double sizesT[5] = {32.0, 64.0, 128.0, 256.0, 512.0};
    static const double ratios[3] = {0.5, 1.0, 2.0};
    AnchorP ap;
    for (int l = 0; l < 5; l++) {
        double area = sizesT[l] * sizesT[l];
        for (int a = 0; a < 3; a++) {
            double w = sqrt(area / ratios[a]);
            double h = w * ratios[a];
            ap.cw[l * 3 + a] = -w / 2.0;
            ap.ch[l * 3 + a] = -h / 2.0;
        }
    }

    // independent of conv output: clear + select init
    clear_aux<<<96, 1024>>>();
    init_select<<<10, 256>>>();

    cudaFuncSetAttribute(conv_head_all, cudaFuncAttributeMaxDynamicSharedMemorySize, CONV_SMEM_B);
    conv_head_all<<<dim3(682, NIMG), 256, CONV_SMEM_B>>>(
        feats, w_conv, b_conv, w_obj, b_obj, w_delta, b_delta, ap);

    for (int r = 0; r < 4; r++) {
        hist_kernel<<<dim3(32, NIMG, 5), 256>>>(r);
        pick_kernel<<<10, 256>>>(r);
    }
    compact_kernel<<<dim3(NIMG, 5), 1024>>>();

    cudaFuncSetAttribute(sort_kernel, cudaFuncAttributeMaxDynamicSharedMemorySize, 65536);
    sort_kernel<<<NIMG, 1024, 65536>>>();
    build_llist<<<10, 1024>>>();
    iou_kernel<<<dim3(4, 32, 10), 256>>>();
    nms_lvl<<<10, 32>>>();
    map_keep<<<10, 1024>>>();
    nms_emit<<<NIMG, 32>>>((float*)d_out);
}

// round 17
// speedup vs baseline: 1.5074x; 1.0291x over previous
#include <cuda_runtime.h>
#include <math.h>
#include <stdint.h>

#define NIMG   2
#define TCAND  4768
#define NWORDS 149
#define STOT   261888
#define SCALE_CLAMP 4.135166556742356f
#define LMASKW (10 * 1000 * 32)

// ------------------ static device scratch ------------------
__device__ float    g_scores[NIMG * STOT];
__device__ float4   g_boxes [NIMG * STOT];
__device__ unsigned g_hist[10 * 256];
__device__ unsigned g_prefix[10];
__device__ unsigned g_krem[10];
__device__ unsigned g_kth[10];
__device__ unsigned g_needed[10];
__device__ int      g_llist[10 * 1000];
__device__ float    g_cand_s[NIMG * TCAND];
__device__ float4   g_cand_b[NIMG * TCAND];
__device__ float    g_sorted_s[NIMG * TCAND];
__device__ float4   g_sorted_b[NIMG * TCAND];
__device__ float4   g_sorted_ob[NIMG * TCAND];
__device__ unsigned g_validw[NIMG * NWORDS];
__device__ unsigned g_lmask[LMASKW];
__device__ unsigned g_keepw[NIMG * NWORDS];

// ------------------ level tables ------------------
__constant__ int   c_H[5]      = {256, 128, 64, 32, 16};
__constant__ int   c_HW[5]     = {65536, 16384, 4096, 1024, 256};
__constant__ float c_stride[5] = {4.f, 8.f, 16.f, 32.f, 64.f};
__constant__ int   c_soff[5]   = {0, 196608, 245760, 258048, 261120};
__constant__ int   c_L[5]      = {196608, 49152, 12288, 3072, 768};
__constant__ int   c_k[5]      = {1000, 1000, 1000, 1000, 768};

struct Feats { const float* p[5]; };
struct AnchorP { double cw[15]; double ch[15]; };

// ------------------ helpers ------------------
__device__ __forceinline__ unsigned f2key(float f) {
    unsigned u = __float_as_uint(f);
    return (u & 0x80000000u) ? ~u : (u | 0x80000000u);
}
__device__ __forceinline__ float clip1024(float v) { return fminf(fmaxf(v, 0.f), 1024.f); }
__device__ __forceinline__ void ffma2(unsigned long long& d, unsigned long long a, unsigned long long b) {
    asm("fma.rn.f32x2 %0, %1, %2, %0;" : "+l"(d) : "l"(a), "l"(b));
}
__device__ __forceinline__ unsigned long long dup2(float x) {
    unsigned long long r;
    asm("mov.b64 %0, {%1, %1};" : "=l"(r) : "f"(x));
    return r;
}
__device__ __forceinline__ float2 unpack2(unsigned long long v) {
    float2 r;
    asm("mov.b64 {%0, %1}, %2;" : "=f"(r.x), "=f"(r.y) : "l"(v));
    return r;
}

// smem layout (floats), BK=32 with T aliasing As/Bs (proven R15 geometry)
#define SM_BS 16384
#define SM_SW 33536
#define TSTRIDE 131
#define CONV_SMEM_B (37376 * 4)

// ------------------ fused FFMA2 conv3x3 + head (+anchor decode), BK=32 ------------------
__global__ __launch_bounds__(256, 1) void conv_head_all(
    Feats feats, const float* __restrict__ wgt, const float* __restrict__ bias,
    const float* __restrict__ w_obj, const float* __restrict__ b_obj,
    const float* __restrict__ w_delta, const float* __restrict__ b_delta,
    AnchorP ap)
{
    extern __shared__ __align__(16) float sm[];
    float* As = sm;
    float* Bs = sm + SM_BS;
    float* T  = sm;
    float* sw = sm + SM_SW;

    const int tid = threadIdx.x;
    const int tx = tid & 15, ty = tid >> 4;

    for (int i = tid; i < 15 * 256; i += 256) {
        int row = i >> 8, c = i & 255;
        sw[i] = (row < 3) ? w_obj[row * 256 + c] : w_delta[(row - 3) * 256 + c];
    }

    int bx = blockIdx.x;
    int lvl, pt;
    if      (bx < 512) { lvl = 0; pt = bx; }
    else if (bx < 640) { lvl = 1; pt = bx - 512; }
    else if (bx < 672) { lvl = 2; pt = bx - 640; }
    else if (bx < 680) { lvl = 3; pt = bx - 672; }
    else               { lvl = 4; pt = bx - 680; }
    const int W  = c_H[lvl];
    const int HW = c_HW[lvl];
    const int n  = blockIdx.y;
    const int p0 = pt * 128;
    const float* inN = feats.p[lvl] + (size_t)n * 256 * HW;

    unsigned long long acc2[8][8];
#pragma unroll
    for (int i = 0; i < 8; i++)
#pragma unroll
        for (int j = 0; j < 8; j++) acc2[i][j] = 0ULL;

    const int ppB  = tid & 127;
    const int kkB0 = (tid >> 7) * 16;
    const float* wrow = wgt + (size_t)tid * 2304;
    const int p   = p0 + ppB;
    const int y0p = p / W;
    const int x0p = p - y0p * W;

    float4 avq[8];
    float  bv[16];

#pragma unroll
    for (int r = 0; r < 8; r++)
        avq[r] = *reinterpret_cast<const float4*>(wrow + r * 4);
#pragma unroll
    for (int q = 0; q < 16; q++) {
        int k  = kkB0 + q;
        int ci = k / 9;
        int rr = k - ci * 9;
        int ky = rr / 3;
        int kx = rr - ky * 3;
        int yy = y0p + ky - 1;
        int xx = x0p + kx - 1;
        float v = 0.f;
        if ((unsigned)yy < (unsigned)W && (unsigned)xx < (unsigned)W)
            v = inN[(size_t)ci * HW + yy * W + xx];
        bv[q] = v;
    }
    {
#pragma unroll
        for (int r = 0; r < 8; r++) {
            float wv[4] = {avq[r].x, avq[r].y, avq[r].z, avq[r].w};
#pragma unroll
            for (int q = 0; q < 4; q++) As[(r * 4 + q) * 256 + tid] = wv[q];
        }
#pragma unroll
        for (int q = 0; q < 16; q++) Bs[(kkB0 + q) * 128 + ppB] = bv[q];
    }
    __syncthreads();

    for (int c0 = 0; c0 < 72; c0++) {
        const int s = c0 & 1;
        const bool more = (c0 + 1) < 72;
        if (more) {
            const float* w2 = wrow + (c0 + 1) * 32;
#pragma unroll
            for (int r = 0; r < 8; r++)
                avq[r] = *reinterpret_cast<const float4*>(w2 + r * 4);
#pragma unroll
            for (int q = 0; q < 16; q++) {
                int k  = (c0 + 1) * 32 + kkB0 + q;
                int ci = k / 9;
                int rr = k - ci * 9;
                int ky = rr / 3;
                int kx = rr - ky * 3;
                int yy = y0p + ky - 1;
                int xx = x0p + kx - 1;
                float v = 0.f;
                if ((unsigned)yy < (unsigned)W && (unsigned)xx < (unsigned)W)
                    v = inN[(size_t)ci * HW + yy * W + xx];
                bv[q] = v;
            }
        }
        const float* Ab = As + s * 32 * 256;
        const float* Bb = Bs + s * 32 * 128;
#pragma unroll
        for (int kk = 0; kk < 32; kk++) {
            unsigned long long a2[8];
#pragma unroll
            for (int q = 0; q < 4; q++) {
                ulonglong2 tt = *reinterpret_cast<const ulonglong2*>(&Ab[kk * 256 + ty * 16 + q * 4]);
                a2[2 * q] = tt.x; a2[2 * q + 1] = tt.y;
            }
            float4 bq0 = *reinterpret_cast<const float4*>(&Bb[kk * 128 + tx * 4]);
            float4 bq1 = *reinterpret_cast<const float4*>(&Bb[kk * 128 + 64 + tx * 4]);
            unsigned long long b2[8];
            b2[0] = dup2(bq0.x); b2[1] = dup2(bq0.y);
            b2[2] = dup2(bq0.z); b2[3] = dup2(bq0.w);
            b2[4] = dup2(bq1.x); b2[5] = dup2(bq1.y);
            b2[6] = dup2(bq1.z); b2[7] = dup2(bq1.w);
#pragma unroll
            for (int i = 0; i < 8; i++)
#pragma unroll
                for (int j = 0; j < 8; j++)
                    ffma2(acc2[i][j], a2[i], b2[j]);
        }
        if (more) {
            float* Ad = As + (s ^ 1) * 32 * 256;
            float* Bd = Bs + (s ^ 1) * 32 * 128;
#pragma unroll
            for (int r = 0; r < 8; r++) {
                float wv[4] = {avq[r].x, avq[r].y, avq[r].z, avq[r].w};
#pragma unroll
                for (int q = 0; q < 4; q++) Ad[(r * 4 + q) * 256 + tid] = wv[q];
            }
#pragma unroll
            for (int q = 0; q < 16; q++) Bd[(kkB0 + q) * 128 + ppB] = bv[q];
        }
        __syncthreads();
    }

#pragma unroll
    for (int i = 0; i < 8; i++) {
        int co = ty * 16 + 2 * i;
        float bb0 = bias[co], bb1 = bias[co + 1];
        float* t0 = T + (size_t)co * TSTRIDE;
        float* t1 = t0 + TSTRIDE;
#pragma unroll
        for (int j = 0; j < 8; j++) {
            float2 v = unpack2(acc2[i][j]);
            int px = (j < 4) ? (tx * 4 + j) : (64 + tx * 4 + (j - 4));
            t0[px] = fmaxf(v.x + bb0, 0.f);
            t1[px] = fmaxf(v.y + bb1, 0.f);
        }
    }
    __syncthreads();

    if (tid < 128) {
        const int px = tid;
        const int pg = p0 + px;
        float acc[15];
#pragma unroll
        for (int i = 0; i < 15; i++) acc[i] = 0.f;
        for (int c = 0; c < 256; c++) {
            float v = T[(size_t)c * TSTRIDE + px];
#pragma unroll
            for (int i = 0; i < 15; i++) acc[i] = fmaf(v, sw[i * 256 + c], acc[i]);
        }
        const float stride = c_stride[lvl];
        float gx = (float)(pg % W) * stride;
        float gy = (float)(pg / W) * stride;
#pragma unroll
        for (int a = 0; a < 3; a++) {
            float s  = acc[a] + b_obj[a];
            float dx = acc[3 + a * 4 + 0] + b_delta[a * 4 + 0];
            float dy = acc[3 + a * 4 + 1] + b_delta[a * 4 + 1];
            float dw = fminf(acc[3 + a * 4 + 2] + b_delta[a * 4 + 2], SCALE_CLAMP);
            float dh = fminf(acc[3 + a * 4 + 3] + b_delta[a * 4 + 3], SCALE_CLAMP);
            double CW = ap.cw[lvl * 3 + a], CH = ap.ch[lvl * 3 + a];
            float x0 = (float)((double)gx + CW);
            float x1 = (float)((double)gx - CW);
            float y0 = (float)((double)gy + CH);
            float y1 = (float)((double)gy - CH);
            float aw = x1 - x0, ah = y1 - y0;
            float acx = x0 + 0.5f * aw, acy = y0 + 0.5f * ah;
            float pcx = dx * aw + acx;
            float pcy = dy * ah + acy;
            float pw = expf(dw) * aw;
            float ph = expf(dh) * ah;
            float4 bx4;
            bx4.x = clip1024(pcx - 0.5f * pw);
            bx4.y = clip1024(pcy - 0.5f * ph);
            bx4.z = clip1024(pcx + 0.5f * pw);
            bx4.w = clip1024(pcy + 0.5f * ph);
            int idx = n * STOT + c_soff[lvl] + pg * 3 + a;
            g_scores[idx] = s;
            g_boxes[idx]  = bx4;
        }
    }
}

// ------------------ fused clear + select init ------------------
__global__ void clear_init() {
    int i = blockIdx.x * 1024 + threadIdx.x;
    for (int w = i; w < LMASKW; w += gridDim.x * 1024) g_lmask[w] = 0u;
    if (i < NIMG * NWORDS) g_keepw[i] = 0u;
    if (i < 10 * 256) g_hist[i] = 0u;
    if (i < 10) { g_prefix[i] = 0u; g_krem[i] = (unsigned)c_k[i >> 1]; }
}

// ------------------ level-parallel radix-select ------------------
__global__ void hist_kernel(int round) {
    __shared__ unsigned sh[256];
    int n = blockIdx.y, lvl = blockIdx.z;
    int s = lvl * 2 + n;
    sh[threadIdx.x] = 0;
    __syncthreads();
    unsigned pfx = g_prefix[s];
    int shift = 24 - 8 * round;
    unsigned maskhi = (round == 0) ? 0u : (0xFFFFFFFFu << (shift + 8));
    int L = c_L[lvl];
    const float* sc = g_scores + n * STOT + c_soff[lvl];
    for (int i = blockIdx.x * blockDim.x + threadIdx.x; i < L; i += gridDim.x * blockDim.x) {
        unsigned key = f2key(sc[i]);
        if (((key ^ pfx) & maskhi) == 0)
            atomicAdd(&sh[(key >> shift) & 255], 1u);
    }
    __syncthreads();
    if (sh[threadIdx.x]) atomicAdd(&g_hist[s * 256 + threadIdx.x], sh[threadIdx.x]);
}

__global__ void pick_kernel(int round) {
    int s = blockIdx.x;
    __shared__ unsigned h[256];
    h[threadIdx.x] = g_hist[s * 256 + threadIdx.x];
    __syncthreads();
    g_hist[s * 256 + threadIdx.x] = 0;
    if (threadIdx.x == 0) {
        int shift = 24 - 8 * round;
        unsigned kr = g_krem[s];
        unsigned cum = 0;
        int bin = 255;
        for (; bin > 0; bin--) {
            unsigned c = h[bin];
            if (cum + c >= kr) break;
            cum += c;
        }
        kr -= cum;
        unsigned pfx = g_prefix[s] | ((unsigned)bin << shift);
        g_prefix[s] = pfx;
        g_krem[s] = kr;
        if (round == 3) { g_kth[s] = pfx; g_needed[s] = kr; }
    }
}

// ------------------ two-pass compaction (2 barriers, order-exact) ------------------
__global__ __launch_bounds__(1024) void compact_kernel() {
    int n = blockIdx.x, lvl = blockIdx.y;
    int s = lvl * 2 + n;
    int L = c_L[lvl], k = c_k[lvl], lvl_off = lvl * 1000;
    unsigned kth = g_kth[s];
    int needed = (int)g_needed[s];
    int G = k - needed;
    const float* scp = g_scores + n * STOT + c_soff[lvl];
    const float4* bxp = g_boxes + n * STOT + c_soff[lvl];

    __shared__ unsigned sg[32], se[32];
    int lane = threadIdx.x & 31, w = threadIdx.x >> 5;
    // warp w owns groups [w*gpw, (w+1)*gpw), each group = 32 consecutive elements
    int ngroups = (L + 31) >> 5;
    int gpw = (ngroups + 31) >> 5;
    int g0 = w * gpw;
    int g1 = min(g0 + gpw, ngroups);

    // pass 1: count
    unsigned cg = 0, ce = 0;
    for (int g = g0; g < g1; g++) {
        int i = g * 32 + lane;
        bool gt = false, eq = false;
        if (i < L) {
            unsigned key = f2key(scp[i]);
            gt = key > kth;
            eq = (key == kth);
        }
        cg += __popc(__ballot_sync(0xffffffffu, gt));
        ce += __popc(__ballot_sync(0xffffffffu, eq));
    }
    if (lane == 0) { sg[w] = cg; se[w] = ce; }
    __syncthreads();
    if (threadIdx.x < 32) {
        unsigned vg = sg[threadIdx.x], ve = se[threadIdx.x];
        unsigned ig = vg, ie = ve;
#pragma unroll
        for (int o = 1; o < 32; o <<= 1) {
            unsigned tg = __shfl_up_sync(0xffffffffu, ig, o);
            unsigned te = __shfl_up_sync(0xffffffffu, ie, o);
            if ((int)threadIdx.x >= o) { ig += tg; ie += te; }
        }
        sg[threadIdx.x] = ig - vg;   // exclusive prefix
        se[threadIdx.x] = ie - ve;
    }
    __syncthreads();

    // pass 2: write
    int rg = (int)sg[w];
    int re = (int)se[w];
    for (int g = g0; g < g1; g++) {
        int i = g * 32 + lane;
        bool gt = false, eq = false;
        float sc = 0.f;
        if (i < L) {
            sc = scp[i];
            unsigned key = f2key(sc);
            gt = key > kth;
            eq = (key == kth);
        }
        unsigned bg = __ballot_sync(0xffffffffu, gt);
        unsigned be = __ballot_sync(0xffffffffu, eq);
        if (gt) {
            int pos = rg + __popc(bg & ((1u << lane) - 1));
            g_cand_s[n * TCAND + lvl_off + pos] = sc;
            g_cand_b[n * TCAND + lvl_off + pos] = bxp[i];
        }
        if (eq) {
            int rank = re + __popc(be & ((1u << lane) - 1));
            if (rank < needed) {
                int pos = G + rank;
                g_cand_s[n * TCAND + lvl_off + pos] = sc;
                g_cand_b[n * TCAND + lvl_off + pos] = bxp[i];
            }
        }
        rg += __popc(bg);
        re += __popc(be);
    }
}

// ------------------ per-image bitonic sort + per-level list build ------------------
__global__ __launch_bounds__(1024) void sort_kernel() {
    extern __shared__ unsigned long long keys[];
    __shared__ unsigned wc[32];
    __shared__ int basep, tot;
    int n = blockIdx.x;
    for (int i = threadIdx.x; i < 8192; i += 1024) {
        unsigned long long kk;
        if (i < TCAND) {
            unsigned sk = f2key(g_cand_s[n * TCAND + i]);
            kk = ((unsigned long long)(~sk) << 32) | (unsigned)i;
        } else kk = ~0ULL;
        keys[i] = kk;
    }
    for (int k = 2; k <= 8192; k <<= 1) {
        for (int j = k >> 1; j > 0; j >>= 1) {
            __syncthreads();
            for (int i = threadIdx.x; i < 8192; i += 1024) {
                int ixj = i ^ j;
                if (ixj > i) {
                    unsigned long long a = keys[i], b = keys[ixj];
                    bool up = ((i & k) == 0);
                    if ((a > b) == up) { keys[i] = b; keys[ixj] = a; }
                }
            }
        }
    }
    __syncthreads();
    for (int i = threadIdx.x; i < TCAND; i += 1024) {
        int j = (int)(unsigned)(keys[i] & 0xffffffffu);
        float s = g_cand_s[n * TCAND + j];
        float4 b = g_cand_b[n * TCAND + j];
        int lvl = (j < 4000) ? (j / 1000) : 4;
        float off = (float)lvl * 1025.0f;
        float4 ob = make_float4(b.x + off, b.y + off, b.z + off, b.w + off);
        g_sorted_s[n * TCAND + i] = s;
        g_sorted_b[n * TCAND + i] = b;
        g_sorted_ob[n * TCAND + i] = ob;
        bool valid = (b.z - b.x > 0.f) && (b.w - b.y > 0.f);
        unsigned bal = __ballot_sync(0xffffffffu, valid);
        if ((threadIdx.x & 31) == 0) g_validw[n * NWORDS + (i >> 5)] = bal;
    }
    // per-level slot lists (slot-ascending), from keys still in smem
    int lane = threadIdx.x & 31, w = threadIdx.x >> 5;
    for (int lvl = 0; lvl < 5; lvl++) {
        __syncthreads();
        if (threadIdx.x == 0) basep = 0;
        __syncthreads();
        int seg = n * 5 + lvl;
        for (int start = 0; start < TCAND; start += 1024) {
            int i = start + threadIdx.x;
            bool pred = false;
            if (i < TCAND) {
                int j = (int)(unsigned)(keys[i] & 0xffffffffu);
                int li = (j < 4000) ? (j / 1000) : 4;
                pred = (li == lvl);
            }
            unsigned bal = __ballot_sync(0xffffffffu, pred);
            if (lane == 0) wc[w] = __popc(bal);
            __syncthreads();
            if (threadIdx.x < 32) {
                unsigned v = wc[threadIdx.x];
                unsigned ig = v;
#pragma unroll
                for (int o = 1; o < 32; o <<= 1) {
                    unsigned t = __shfl_up_sync(0xffffffffu, ig, o);
                    if ((int)threadIdx.x >= o) ig += t;
                }
                wc[threadIdx.x] = ig - v;
                if (threadIdx.x == 31) tot = (int)ig;
            }
            __syncthreads();
            if (pred) {
                int pos = basep + (int)wc[w] + __popc(bal & ((1u << lane) - 1));
                g_llist[seg * 1000 + pos] = i;
            }
            __syncthreads();
            if (threadIdx.x == 0) basep += tot;
        }
    }
}

// ------------------ IoU: same-level pairs, per-level mask (je > ie) ------------------
__global__ __launch_bounds__(256) void iou_kernel() {
    int seg = blockIdx.z;
    int n = seg / 5, lvl = seg % 5;
    int kl = c_k[lvl];
    int i0 = blockIdx.y * 32;
    if (i0 >= kl) return;

    __shared__ float4 sbx[32];
    __shared__ float  sar[32];
    if (threadIdx.x < 32) {
        int ie = i0 + threadIdx.x;
        if (ie < kl) {
            int sl = g_llist[seg * 1000 + ie];
            float4 b = g_sorted_ob[n * TCAND + sl];
            sbx[threadIdx.x] = b;
            sar[threadIdx.x] = (b.z - b.x) * (b.w - b.y);
        }
    }
    __syncthreads();

    int je = blockIdx.x * 256 + threadIdx.x;
    if (je >= kl || je <= i0) return;
    int slj = g_llist[seg * 1000 + je];
    float4 bj = g_sorted_ob[n * TCAND + slj];
    float areaj = (bj.z - bj.x) * (bj.w - bj.y);

#pragma unroll 4
    for (int ii = 0; ii < 32; ii++) {
        int ie = i0 + ii;
        if (ie >= kl) break;
        if (je > ie) {
            float4 bi = sbx[ii];
            float areai = sar[ii];
            float ltx = fmaxf(bi.x, bj.x), lty = fmaxf(bi.y, bj.y);
            float rbx = fminf(bi.z, bj.z), rby = fminf(bi.w, bj.w);
            float iw = fmaxf(rbx - ltx, 0.f), ih = fmaxf(rby - lty, 0.f);
            float inter = iw * ih;
            float uni = areai + areaj - inter;
            float iou = (uni > 0.f) ? (inter / uni) : 0.f;
            if (iou > 0.7f)
                atomicOr(&g_lmask[((size_t)seg * 1000 + ie) * 32 + (je >> 5)],
                         1u << (je & 31));
        }
    }
}

// ------------------ per-level greedy scan + keep mapping (10 parallel warps) ------------------
__global__ void nms_lvl() {
    int seg = blockIdx.x;
    int lvl = seg % 5;
    int n = seg / 5;
    int kl = c_k[lvl];
    int lane = threadIdx.x;
    int lo = lane * 32;
    unsigned keep;
    if (kl >= lo + 32) keep = 0xFFFFFFFFu;
    else if (kl > lo)  keep = (1u << (kl - lo)) - 1u;
    else               keep = 0u;

    unsigned cur = g_lmask[((size_t)seg * 1000 + 0) * 32 + lane];
    for (int e = 0; e < kl; e++) {
        unsigned nxt = (e + 1 < kl) ? g_lmask[((size_t)seg * 1000 + e + 1) * 32 + lane] : 0u;
        int owner = e >> 5;
        unsigned kw = __shfl_sync(0xffffffffu, keep, owner);
        if ((kw >> (e & 31)) & 1u)
            keep &= ~cur;
        cur = nxt;
    }
    // map kept entries to global slot keep words (lane owns entries [lo, lo+32))
#pragma unroll 1
    for (int b = 0; b < 32; b++) {
        int e = lo + b;
        if (e < kl && ((keep >> b) & 1u)) {
            int slot = g_llist[seg * 1000 + e];
            atomicOr(&g_keepw[n * NWORDS + (slot >> 5)], 1u << (slot & 31));
        }
    }
}

// ------------------ ordered emission (1 warp / image) ------------------
__global__ void nms_emit(float* __restrict__ out) {
    int n = blockIdx.x;
    int lane = threadIdx.x;
    unsigned keep[5];
#pragma unroll
    for (int q = 0; q < 5; q++) {
        int w = lane * 5 + q;
        keep[q] = (w < NWORDS) ? (g_keepw[n * NWORDS + w] & g_validw[n * NWORDS + w]) : 0u;
    }
    int mycnt = 0;
#pragma unroll
    for (int q = 0; q < 5; q++) mycnt += __popc(keep[q]);
    int incl = mycnt;
#pragma unroll
    for (int o = 1; o < 32; o <<= 1) {
        int t = __shfl_up_sync(0xffffffffu, incl, o);
        if (lane >= o) incl += t;
    }
    int nk = __shfl_sync(0xffffffffu, incl, 31);
    int run = incl - mycnt;
    float ninf = __int_as_float((int)0xff800000u);
    float* outS = out + 8000;
#pragma unroll
    for (int q = 0; q < 5; q++) {
        int w = lane * 5 + q;
        if (w >= NWORDS) continue;
        unsigned kwv = keep[q];
        for (int b = 0; b < 32; b++) {
            int i = w * 32 + b;
            int ones_before = run + __popc(kwv & ((1u << b) - 1));
            bool kept = (kwv >> b) & 1u;
            int pos = kept ? ones_before : (nk + (i - ones_before));
            if (pos < 1000) {
                float4 bx = g_sorted_b[n * TCAND + i];
                float* ob = out + ((size_t)n * 1000 + pos) * 4;
                ob[0] = bx.x; ob[1] = bx.y; ob[2] = bx.z; ob[3] = bx.w;
                outS[n * 1000 + pos] = kept ? g_sorted_s[n * TCAND + i] : ninf;
            }
        }
        run += __popc(kwv);
    }
}

// ------------------ launch ------------------
extern "C" void kernel_launch(void* const* d_in, const int* in_sizes, int n_in,
                              void* d_out, int out_size) {
    (void)in_sizes; (void)n_in; (void)out_size;
    Feats feats;
    for (int i = 0; i < 5; i++) feats.p[i] = (const float*)d_in[i];
    const float* w_conv  = (const float*)d_in[5];
    const float* b_conv  = (const float*)d_in[6];
    const float* w_obj   = (const float*)d_in[7];
    const float* b_obj   = (const float*)d_in[8];
    const float* w_delta = (const float*)d_in[9];
    const float* b_delta = (const float*)d_in[10];

    static const double sizesT[5] = {32.0, 64.0, 128.0, 256.0, 512.0};
    static const double ratios[3] = {0.5, 1.0, 2.0};
    AnchorP ap;
    for (int l = 0; l < 5; l++) {
        double area = sizesT[l] * sizesT[l];
        for (int a = 0; a < 3; a++) {
            double w = sqrt(area / ratios[a]);
            double h = w * ratios[a];
            ap.cw[l * 3 + a] = -w / 2.0;
            ap.ch[l * 3 + a] = -h / 2.0;
        }
    }

    clear_init<<<96, 1024>>>();

    cudaFuncSetAttribute(conv_head_all, cudaFuncAttributeMaxDynamicSharedMemorySize, CONV_SMEM_B);
    conv_head_all<<<dim3(682, NIMG), 256, CONV_SMEM_B>>>(
        feats, w_conv, b_conv, w_obj, b_obj, w_delta, b_delta, ap);

    for (int r = 0; r < 4; r++) {
        hist_kernel<<<dim3(32, NIMG, 5), 256>>>(r);
        pick_kernel<<<10, 256>>>(r);
    }
    compact_kernel<<<dim3(NIMG, 5), 1024>>>();

    cudaFuncSetAttribute(sort_kernel, cudaFuncAttributeMaxDynamicSharedMemorySize, 65536);
    sort_kernel<<<NIMG, 1024, 65536>>>();
    iou_kernel<<<dim3(4, 32, 10), 256>>>();
    nms_lvl<<<10, 32>>>();
    nms_emit<<<NIMG, 32>>>((float*)d_out);
}